// round 15
// baseline (speedup 1.0000x reference)
#include <cuda_runtime.h>
#include <cuda_bf16.h>
#include <math.h>
#include <stdint.h>

// ---------------------------------------------------------------------------
// Problem constants
// ---------------------------------------------------------------------------
constexpr int BB = 2;     // batch
constexpr int SS = 1024;  // seq len
constexpr int DD = 1024;  // model dim
constexpr int HH = 16;    // heads
constexpr int LL = 6;     // layers
constexpr int VV = 256;   // vocab
constexpr int HD = 64;    // head dim
constexpr int DF = 512;   // ffn dim
constexpr int QKW = 2048; // combined q|k width
constexpr float ATT_SCALE = 0.125f;  // 1/sqrt(64)

// ---------------------------------------------------------------------------
// Scratch (static device globals -- no allocations allowed)
// ---------------------------------------------------------------------------
__device__ float g_t1 [BB * SS * DD];                 // pre-LN fp32
__device__ float g_h2 [BB * SS * DD];                 // pre-LN fp32
__device__ float g_qe [(size_t)BB * HH * SS * SS];    // 134 MB
__device__ float g_lg [(size_t)BB * HH * SS * SS];    // exp(logits), 134 MB
__device__ float g_rate[DD];
__device__ float g_ps [(size_t)BB * HH * SS * 16];    // per-(row,tile,half) sumexp

// split activation buffers
__device__ __nv_bfloat16 g_xh [BB * SS * DD], g_xl [BB * SS * DD];  // layer in
__device__ __nv_bfloat16 g_qkh[BB * SS * QKW], g_qkl[BB * SS * QKW]; // q|k
__device__ __nv_bfloat16 g_vth[BB * DD * SS], g_vtl[BB * DD * SS];  // v^T per head
__device__ __nv_bfloat16 g_ath[BB * SS * DD], g_atl[BB * SS * DD];  // attn out
__device__ __nv_bfloat16 g_ffh[BB * SS * DF], g_ffl[BB * SS * DF];
__device__ __nv_bfloat16 g_eh [LL * SS * HD], g_el [LL * SS * HD];

// bf16 split weight buffers ([N, K] transposed, hi/lo)
__device__ __nv_bfloat16 g_wqk_h[LL * QKW * DD], g_wqk_l[LL * QKW * DD];
__device__ __nv_bfloat16 g_wv_h[LL * DD * DD],  g_wv_l[LL * DD * DD];
__device__ __nv_bfloat16 g_wo_h[LL * DD * DD],  g_wo_l[LL * DD * DD];
__device__ __nv_bfloat16 g_w1_h[LL * DF * DD],  g_w1_l[LL * DF * DD];
__device__ __nv_bfloat16 g_w2_h[LL * DD * DF],  g_w2_l[LL * DD * DF];
__device__ __nv_bfloat16 g_wf_h[VV * DD],       g_wf_l[VV * DD];

// ---------------------------------------------------------------------------
// PTX helpers (mma.sync / ldmatrix / cp.async -- standard ISA, sm_80+)
// ---------------------------------------------------------------------------
__device__ __forceinline__ uint32_t smem_u32(const void* p) {
    uint32_t a;
    asm("{ .reg .u64 t; cvta.to.shared.u64 t, %1; cvt.u32.u64 %0, t; }"
        : "=r"(a) : "l"(p));
    return a;
}
__device__ __forceinline__ void cpasync16(uint32_t s, const void* g) {
    asm volatile("cp.async.ca.shared.global [%0], [%1], 16;"
                 :: "r"(s), "l"(g) : "memory");
}
__device__ __forceinline__ void ldm_x4(uint32_t a, uint32_t r[4]) {
    asm volatile("ldmatrix.sync.aligned.m8n8.x4.shared.b16 {%0,%1,%2,%3}, [%4];"
                 : "=r"(r[0]), "=r"(r[1]), "=r"(r[2]), "=r"(r[3]) : "r"(a));
}
__device__ __forceinline__ void mma_bf16(float c[4], const uint32_t a[4],
                                         const uint32_t b[2]) {
    asm volatile("mma.sync.aligned.m16n8k16.row.col.f32.bf16.bf16.f32 "
                 "{%0,%1,%2,%3}, {%4,%5,%6,%7}, {%8,%9}, {%0,%1,%2,%3};"
                 : "+f"(c[0]), "+f"(c[1]), "+f"(c[2]), "+f"(c[3])
                 : "r"(a[0]), "r"(a[1]), "r"(a[2]), "r"(a[3]),
                   "r"(b[0]), "r"(b[1]));
}
__device__ __forceinline__ uint32_t pack_bf2(float a, float b) {
    __nv_bfloat162 t = __floats2bfloat162_rn(a, b);
    return *(uint32_t*)&t;
}
__device__ __forceinline__ float bf_hi(float v) {
    return __bfloat162float(__float2bfloat16(v));
}

// ---------------------------------------------------------------------------
// Unified batched split-bf16 HMMA GEMM.
// OUT: 0 fp32 C; 1 split bf16; 2 split bf16 transposed (smem staged);
//      3 attention-logit mode: v = (acc + qe_gather)*scale + pad_mask (or
//        -1e30 beyond causal); exp(v) written fp32 to C; per-(row,tile,half)
//        sum of exp(v) written to psum (Cl), qe via Ch, tokens x via bias.
// ---------------------------------------------------------------------------
template<int BN, int SKIP, bool KCAP, int OUT, bool RELU>
__global__ __launch_bounds__(256, 2)
void gemm_mma(const __nv_bfloat16* __restrict__ Ahi, const __nv_bfloat16* __restrict__ Alo,
              const __nv_bfloat16* __restrict__ Bhi, const __nv_bfloat16* __restrict__ Blo,
              const float* __restrict__ bias, float* __restrict__ C,
              __nv_bfloat16* __restrict__ Ch, __nv_bfloat16* __restrict__ Cl,
              int K, int lda, int ldb, int ldc, int zdiv,
              long long sA1, long long sA2,
              long long sB1, long long sB2,
              long long sC1, long long sC2)
{
    constexpr int ABY = 10240;            // 128 rows * 80B
    constexpr int BBY = BN * 80;
    constexpr int STG = 2 * ABY + 2 * BBY;
    constexpr int NT  = BN / 16;
    constexpr int BN2 = BN / 2;
    constexpr int TP  = 136;              // transpose-stage pitch (bf16 elems)

    const int m0 = blockIdx.y * 128;
    const int n0 = blockIdx.x * BN;
    if (SKIP == 1 && (m0 + n0 + 127 + BN - 1 < SS - 1)) return;
    if (SKIP == 2 && (n0 >= m0 + 128)) return;

    extern __shared__ char dynsmem[];
    const uint32_t sbase = smem_u32(dynsmem);
    const int tid  = threadIdx.x;
    const int lane = tid & 31;
    const int warp = tid >> 5;
    const int wm = warp & 3;
    const int wn = warp >> 2;

    const int z  = blockIdx.z;
    const int zb = z / zdiv;
    const int zh = z % zdiv;
    Ahi += (size_t)zb * sA1 + (size_t)zh * sA2;
    Alo += (size_t)zb * sA1 + (size_t)zh * sA2;
    Bhi += (size_t)zb * sB1 + (size_t)zh * sB2;
    Blo += (size_t)zb * sB1 + (size_t)zh * sB2;
    if (OUT == 0 || OUT == 3) C += (size_t)zb * sC1 + (size_t)zh * sC2;
    if (OUT == 1 || OUT == 2) { Ch += (size_t)zb * sC1 + (size_t)zh * sC2;
                                Cl += (size_t)zb * sC1 + (size_t)zh * sC2; }
    const float* qeB = (OUT == 3)
        ? ((const float*)Ch + (size_t)zb * sC1 + (size_t)zh * sC2) : nullptr;
    float* psB = (OUT == 3) ? ((float*)Cl + (size_t)z * SS * 16) : nullptr;
    const int* xB = (OUT == 3) ? ((const int*)bias + (size_t)zb * SS) : nullptr;

    float acc[2][NT][4];
#pragma unroll
    for (int mt = 0; mt < 2; ++mt)
#pragma unroll
        for (int nt = 0; nt < NT; ++nt)
#pragma unroll
            for (int r = 0; r < 4; ++r) acc[mt][nt][r] = 0.f;

    const int Keff = KCAP ? min(K, m0 + 128) : K;
    const int nch  = Keff >> 5;

    auto load_stage = [&](int c) {
        const int k0c = c << 5;
        const uint32_t sb = sbase + (c & 1) * STG;
#pragma unroll
        for (int i = 0; i < 2; ++i) {
            const int u = tid + i * 256;
            const int row = u >> 2, seg = u & 3;
            const uint32_t so = sb + row * 80 + seg * 16;
            const size_t ga = (size_t)(m0 + row) * lda + k0c + seg * 8;
            cpasync16(so,       Ahi + ga);
            cpasync16(so + ABY, Alo + ga);
        }
        constexpr int BU = (BN * 4) / 256;
#pragma unroll
        for (int i = 0; i < BU; ++i) {
            const int u = tid + i * 256;
            const int row = u >> 2, seg = u & 3;
            const uint32_t so = sb + 2 * ABY + row * 80 + seg * 16;
            const size_t gb = (size_t)(n0 + row) * ldb + k0c + seg * 8;
            cpasync16(so,       Bhi + gb);
            cpasync16(so + BBY, Blo + gb);
        }
        asm volatile("cp.async.commit_group;" ::: "memory");
    };

    load_stage(0);

    const int lr  = lane & 7;
    const int sel = lane >> 3;
    const int a_row_off = lr + ((sel & 1) << 3);
    const int a_k_off   = (sel >> 1) << 3;
    const int b_n_off   = lr + ((sel >> 1) << 3);
    const int b_k_off   = (sel & 1) << 3;

    for (int c = 0; c < nch; ++c) {
        if (c + 1 < nch) {
            load_stage(c + 1);
            asm volatile("cp.async.wait_group 1;" ::: "memory");
        } else {
            asm volatile("cp.async.wait_group 0;" ::: "memory");
        }
        __syncthreads();
        const uint32_t sb = sbase + (c & 1) * STG;

#pragma unroll
        for (int ks = 0; ks < 2; ++ks) {
            const int kk = ks << 4;
            uint32_t ah[2][4], al[2][4], bb[NT][2];
#pragma unroll
            for (int mt = 0; mt < 2; ++mt) {
                const int row = wm * 32 + mt * 16 + a_row_off;
                const uint32_t ad = sb + row * 80 + (kk + a_k_off) * 2;
                ldm_x4(ad, ah[mt]);
                ldm_x4(ad + ABY, al[mt]);
            }
#pragma unroll
            for (int p = 0; p < NT / 2; ++p) {
                const int n = wn * BN2 + p * 16 + b_n_off;
                uint32_t r[4];
                ldm_x4(sb + 2 * ABY + n * 80 + (kk + b_k_off) * 2, r);
                bb[2 * p][0]     = r[0]; bb[2 * p][1]     = r[1];
                bb[2 * p + 1][0] = r[2]; bb[2 * p + 1][1] = r[3];
            }
#pragma unroll
            for (int mt = 0; mt < 2; ++mt)
#pragma unroll
                for (int nt = 0; nt < NT; ++nt)
                    mma_bf16(acc[mt][nt], ah[mt], bb[nt]);
#pragma unroll
            for (int mt = 0; mt < 2; ++mt)
#pragma unroll
                for (int nt = 0; nt < NT; ++nt)
                    mma_bf16(acc[mt][nt], al[mt], bb[nt]);
#pragma unroll
            for (int p = 0; p < NT / 2; ++p) {
                const int n = wn * BN2 + p * 16 + b_n_off;
                uint32_t r[4];
                ldm_x4(sb + 2 * ABY + BBY + n * 80 + (kk + b_k_off) * 2, r);
                bb[2 * p][0]     = r[0]; bb[2 * p][1]     = r[1];
                bb[2 * p + 1][0] = r[2]; bb[2 * p + 1][1] = r[3];
            }
#pragma unroll
            for (int mt = 0; mt < 2; ++mt)
#pragma unroll
                for (int nt = 0; nt < NT; ++nt)
                    mma_bf16(acc[mt][nt], ah[mt], bb[nt]);
        }
        __syncthreads();
    }

    const int rbase = m0 + wm * 32 + (lane >> 2);
    const int cbase = n0 + wn * BN2 + 2 * (lane & 3);
    __nv_bfloat16* tsh = (__nv_bfloat16*)dynsmem;            // OUT==2 staging
    __nv_bfloat16* tsl = (__nv_bfloat16*)(dynsmem + (size_t)BN * TP * 2);
#pragma unroll
    for (int mt = 0; mt < 2; ++mt) {
        const int i0r = rbase + mt * 16;
        const int i1r = i0r + 8;
        float e0 = 0.f, e1 = 0.f;                            // OUT==3 sums
#pragma unroll
        for (int nt = 0; nt < NT; ++nt) {
            const int col = cbase + nt * 8;
            float b0v = 0.f, b1v = 0.f;
            if (OUT != 3 && bias) { b0v = bias[col]; b1v = bias[col + 1]; }
            float v0 = acc[mt][nt][0] + b0v;
            float v1 = acc[mt][nt][1] + b1v;
            float v2 = acc[mt][nt][2] + b0v;
            float v3 = acc[mt][nt][3] + b1v;
            if (RELU) {
                v0 = fmaxf(v0, 0.f); v1 = fmaxf(v1, 0.f);
                v2 = fmaxf(v2, 0.f); v3 = fmaxf(v3, 0.f);
            }
            if (OUT == 0) {
                *(float2*)&C[(size_t)i0r * ldc + col] = make_float2(v0, v1);
                *(float2*)&C[(size_t)i1r * ldc + col] = make_float2(v2, v3);
            } else if (OUT == 1) {
                const float h0 = bf_hi(v0), h1 = bf_hi(v1);
                const float h2 = bf_hi(v2), h3 = bf_hi(v3);
                *(uint32_t*)&Ch[(size_t)i0r * ldc + col] = pack_bf2(h0, h1);
                *(uint32_t*)&Ch[(size_t)i1r * ldc + col] = pack_bf2(h2, h3);
                *(uint32_t*)&Cl[(size_t)i0r * ldc + col] = pack_bf2(v0 - h0, v1 - h1);
                *(uint32_t*)&Cl[(size_t)i1r * ldc + col] = pack_bf2(v2 - h2, v3 - h3);
            } else if (OUT == 2) {
                const float vv[4] = {v0, v1, v2, v3};
#pragma unroll
                for (int e = 0; e < 4; ++e) {
                    const int cc = col - n0 + (e & 1);
                    const int rr = i0r - m0 + (e >> 1) * 8;
                    const __nv_bfloat16 hb = __float2bfloat16(vv[e]);
                    tsh[cc * TP + rr] = hb;
                    tsl[cc * TP + rr] =
                        __float2bfloat16(vv[e] - __bfloat162float(hb));
                }
            } else {  // OUT == 3: attention-logit epilogue, stores exp(v)
                const int j0 = col, j1 = col + 1;
                const float p0 = (xB[j0] == 0) ? -1e9f : 0.f;
                const float p1 = (xB[j1] == 0) ? -1e9f : 0.f;
                v0 = (j0 <= i0r)
                   ? (v0 + qeB[(size_t)i0r * SS + (SS - 1 - i0r) + j0]) * ATT_SCALE + p0
                   : -1e30f;
                v1 = (j1 <= i0r)
                   ? (v1 + qeB[(size_t)i0r * SS + (SS - 1 - i0r) + j1]) * ATT_SCALE + p1
                   : -1e30f;
                v2 = (j0 <= i1r)
                   ? (v2 + qeB[(size_t)i1r * SS + (SS - 1 - i1r) + j0]) * ATT_SCALE + p0
                   : -1e30f;
                v3 = (j1 <= i1r)
                   ? (v3 + qeB[(size_t)i1r * SS + (SS - 1 - i1r) + j1]) * ATT_SCALE + p1
                   : -1e30f;
                const float ex0 = __expf(v0), ex1 = __expf(v1);
                const float ex2 = __expf(v2), ex3 = __expf(v3);
                *(float2*)&C[(size_t)i0r * ldc + col] = make_float2(ex0, ex1);
                *(float2*)&C[(size_t)i1r * ldc + col] = make_float2(ex2, ex3);
                e0 += ex0 + ex1;
                e1 += ex2 + ex3;
            }
        }
        if (OUT == 3) {
            e0 += __shfl_xor_sync(0xffffffffu, e0, 1);
            e0 += __shfl_xor_sync(0xffffffffu, e0, 2);
            e1 += __shfl_xor_sync(0xffffffffu, e1, 1);
            e1 += __shfl_xor_sync(0xffffffffu, e1, 2);
            if ((lane & 3) == 0) {
                psB[(size_t)i0r * 16 + (n0 >> 7) * 2 + wn] = e0;
                psB[(size_t)i1r * 16 + (n0 >> 7) * 2 + wn] = e1;
            }
        }
    }
    if (OUT == 2) {
        __syncthreads();
#pragma unroll
        for (int p = 0; p < BN / 16; ++p) {
            const int idx = tid + p * 256;
            const int row = idx >> 4, seg = idx & 15;
            const uint4 vh = *(const uint4*)&tsh[row * TP + seg * 8];
            const uint4 vl = *(const uint4*)&tsl[row * TP + seg * 8];
            *(uint4*)&Ch[(size_t)(n0 + row) * ldc + m0 + seg * 8] = vh;
            *(uint4*)&Cl[(size_t)(n0 + row) * ldc + m0 + seg * 8] = vl;
        }
    }
}

// ---------------------------------------------------------------------------
// AV GEMM: attn = P @ v, reading stored exp-values directly; invS computed
// inline from psum partials. B = v^T (split bf16). K capped causally.
// ---------------------------------------------------------------------------
constexpr int AV_AP   = 36;                       // A pitch (floats)
constexpr int AV_ABY  = 128 * AV_AP * 4;          // 18432 B
constexpr int AV_BBY  = 64 * 80;                  // 5120 B
constexpr int AV_STG  = AV_ABY + 2 * AV_BBY;      // 28672
constexpr int AV_SMEM = 2 * AV_STG;               // 57344

__global__ __launch_bounds__(256, 2)
void av_gemm(const float* __restrict__ lg, const float* __restrict__ ps,
             const __nv_bfloat16* __restrict__ vth, const __nv_bfloat16* __restrict__ vtl,
             __nv_bfloat16* __restrict__ oh, __nv_bfloat16* __restrict__ ol)
{
    extern __shared__ char dynsmem[];
    const uint32_t sbase = smem_u32(dynsmem);
    float* Asf = (float*)dynsmem;
    const int tid  = threadIdx.x;
    const int lane = tid & 31;
    const int warp = tid >> 5;
    const int wm = warp & 3;
    const int wn = warp >> 2;
    const int m0 = blockIdx.y * 128;
    const int bh = blockIdx.z;
    const int b  = bh >> 4;
    const int h  = bh & 15;

    const float* A = lg + (size_t)bh * SS * SS;
    const __nv_bfloat16* Bh = vth + ((size_t)b * DD + h * HD) * SS;
    const __nv_bfloat16* Bl = vtl + ((size_t)b * DD + h * HD) * SS;

    // inline invS from psum partials (deterministic fixed order)
    const int rr0 = m0 + wm * 32 + (lane >> 2);
    float iv[4];
#pragma unroll
    for (int r = 0; r < 4; ++r) {
        const int row = rr0 + r * 8;
        const float* pp = ps + ((size_t)bh * SS + row) * 16;
        const int nt2 = ((row >> 7) + 1) * 2;
        float s = 0.f;
        for (int t = 0; t < nt2; ++t) s += pp[t];
        iv[r] = 1.f / s;
    }

    float acc[2][4][4];
#pragma unroll
    for (int mt = 0; mt < 2; ++mt)
#pragma unroll
        for (int nt = 0; nt < 4; ++nt)
#pragma unroll
            for (int r = 0; r < 4; ++r) acc[mt][nt][r] = 0.f;

    const int Keff = min(SS, m0 + 128);
    const int nch  = Keff >> 5;

    auto load_stage = [&](int c) {
        const int k0c = c << 5;
        const uint32_t sb = sbase + (c & 1) * AV_STG;
#pragma unroll
        for (int i = 0; i < 4; ++i) {
            const int u = tid + i * 256;
            const int row = u >> 3, seg = u & 7;
            cpasync16(sb + row * (AV_AP * 4) + seg * 16,
                      A + (size_t)(m0 + row) * SS + k0c + seg * 4);
        }
        {
            const int row = tid >> 2, seg = tid & 3;
            const uint32_t so = sb + AV_ABY + row * 80 + seg * 16;
            const size_t gb = (size_t)row * SS + k0c + seg * 8;
            cpasync16(so,          Bh + gb);
            cpasync16(so + AV_BBY, Bl + gb);
        }
        asm volatile("cp.async.commit_group;" ::: "memory");
    };

    load_stage(0);

    const int lr  = lane & 7;
    const int sel = lane >> 3;
    const int b_n_off = lr + ((sel >> 1) << 3);
    const int b_k_off = (sel & 1) << 3;

    for (int c = 0; c < nch; ++c) {
        if (c + 1 < nch) {
            load_stage(c + 1);
            asm volatile("cp.async.wait_group 1;" ::: "memory");
        } else {
            asm volatile("cp.async.wait_group 0;" ::: "memory");
        }
        __syncthreads();
        const float* Af = Asf + ((c & 1) ? AV_STG / 4 : 0);
        const uint32_t sbB = sbase + (c & 1) * AV_STG + AV_ABY;

#pragma unroll
        for (int ks = 0; ks < 2; ++ks) {
            const int kk = ks << 4;
            const int c0 = kk + (lane & 3) * 2;
            uint32_t aH[2][4], aL[2][4], bb[4][2];
#pragma unroll
            for (int mt = 0; mt < 2; ++mt) {
                const float* Ar = Af + (wm * 32 + mt * 16 + (lane >> 2)) * AV_AP;
                const float2 x00 = *(const float2*)(Ar + c0);
                const float2 x10 = *(const float2*)(Ar + 8 * AV_AP + c0);
                const float2 x01 = *(const float2*)(Ar + c0 + 8);
                const float2 x11 = *(const float2*)(Ar + 8 * AV_AP + c0 + 8);
                const float i0 = iv[mt * 2], i1 = iv[mt * 2 + 1];
                const float p0 = x00.x * i0, p1 = x00.y * i0;
                const float p2 = x10.x * i1, p3 = x10.y * i1;
                const float p4 = x01.x * i0, p5 = x01.y * i0;
                const float p6 = x11.x * i1, p7 = x11.y * i1;
                const float h0 = bf_hi(p0), h1 = bf_hi(p1), h2 = bf_hi(p2), h3 = bf_hi(p3);
                const float h4 = bf_hi(p4), h5 = bf_hi(p5), h6 = bf_hi(p6), h7 = bf_hi(p7);
                aH[mt][0] = pack_bf2(h0, h1); aH[mt][1] = pack_bf2(h2, h3);
                aH[mt][2] = pack_bf2(h4, h5); aH[mt][3] = pack_bf2(h6, h7);
                aL[mt][0] = pack_bf2(p0 - h0, p1 - h1);
                aL[mt][1] = pack_bf2(p2 - h2, p3 - h3);
                aL[mt][2] = pack_bf2(p4 - h4, p5 - h5);
                aL[mt][3] = pack_bf2(p6 - h6, p7 - h7);
            }
#pragma unroll
            for (int np = 0; np < 2; ++np) {
                const int n = wn * 32 + np * 16 + b_n_off;
                uint32_t r[4];
                ldm_x4(sbB + n * 80 + (kk + b_k_off) * 2, r);
                bb[2 * np][0]     = r[0]; bb[2 * np][1]     = r[1];
                bb[2 * np + 1][0] = r[2]; bb[2 * np + 1][1] = r[3];
            }
#pragma unroll
            for (int mt = 0; mt < 2; ++mt)
#pragma unroll
                for (int nt = 0; nt < 4; ++nt)
                    mma_bf16(acc[mt][nt], aH[mt], bb[nt]);
#pragma unroll
            for (int mt = 0; mt < 2; ++mt)
#pragma unroll
                for (int nt = 0; nt < 4; ++nt)
                    mma_bf16(acc[mt][nt], aL[mt], bb[nt]);
#pragma unroll
            for (int np = 0; np < 2; ++np) {
                const int n = wn * 32 + np * 16 + b_n_off;
                uint32_t r[4];
                ldm_x4(sbB + AV_BBY + n * 80 + (kk + b_k_off) * 2, r);
                bb[2 * np][0]     = r[0]; bb[2 * np][1]     = r[1];
                bb[2 * np + 1][0] = r[2]; bb[2 * np + 1][1] = r[3];
            }
#pragma unroll
            for (int mt = 0; mt < 2; ++mt)
#pragma unroll
                for (int nt = 0; nt < 4; ++nt)
                    mma_bf16(acc[mt][nt], aH[mt], bb[nt]);
        }
        __syncthreads();
    }

    __nv_bfloat16* Oh = oh + ((size_t)b * SS) * DD + h * HD;
    __nv_bfloat16* Ol = ol + ((size_t)b * SS) * DD + h * HD;
    const int cb = wn * 32 + 2 * (lane & 3);
#pragma unroll
    for (int mt = 0; mt < 2; ++mt) {
        const int i0r = rr0 + mt * 16;
        const int i1r = i0r + 8;
#pragma unroll
        for (int nt = 0; nt < 4; ++nt) {
            const int col = cb + nt * 8;
            const float v0 = acc[mt][nt][0], v1 = acc[mt][nt][1];
            const float v2 = acc[mt][nt][2], v3 = acc[mt][nt][3];
            const float h0 = bf_hi(v0), h1 = bf_hi(v1);
            const float h2 = bf_hi(v2), h3 = bf_hi(v3);
            *(uint32_t*)&Oh[(size_t)i0r * DD + col] = pack_bf2(h0, h1);
            *(uint32_t*)&Oh[(size_t)i1r * DD + col] = pack_bf2(h2, h3);
            *(uint32_t*)&Ol[(size_t)i0r * DD + col] = pack_bf2(v0 - h0, v1 - h1);
            *(uint32_t*)&Ol[(size_t)i1r * DD + col] = pack_bf2(v2 - h2, v3 - h3);
        }
    }
}

// ---------------------------------------------------------------------------
// Weight transpose + bf16 hi/lo split (64x64 tiles, packed stores)
// ---------------------------------------------------------------------------
__global__ __launch_bounds__(256)
void conv_w(const float* __restrict__ W, __nv_bfloat16* __restrict__ hi,
            __nv_bfloat16* __restrict__ lo, int K, int N, long long lstride)
{
    __shared__ float t[64][65];   // [n][k]
    const int l = blockIdx.z;
    W  += (size_t)l * K * N;
    hi += (size_t)l * lstride;
    lo += (size_t)l * lstride;
    const int k0 = blockIdx.y * 64, n0 = blockIdx.x * 64;
    const int tid = threadIdx.x;
    const int tc = tid & 31;
    const int tr = tid >> 5;
#pragma unroll
    for (int i = 0; i < 8; ++i) {
        const int kk = tr + i * 8;
        const float2 v = *(const float2*)&W[(size_t)(k0 + kk) * N + n0 + tc * 2];
        t[tc * 2][kk]     = v.x;
        t[tc * 2 + 1][kk] = v.y;
    }
    __syncthreads();
    const int kp = (tid & 31) * 2;
    const int nb = tid >> 5;
#pragma unroll
    for (int i = 0; i < 8; ++i) {
        const int n = nb + i * 8;
        const float a = t[n][kp], b = t[n][kp + 1];
        const float ha = bf_hi(a), hb = bf_hi(b);
        *(uint32_t*)&hi[(size_t)(n0 + n) * K + k0 + kp] = pack_bf2(ha, hb);
        *(uint32_t*)&lo[(size_t)(n0 + n) * K + k0 + kp] = pack_bf2(a - ha, b - hb);
    }
}

// elementwise hi/lo split (for E)
__global__ void split_act(const float* __restrict__ x, __nv_bfloat16* __restrict__ hi,
                          __nv_bfloat16* __restrict__ lo, int n4)
{
    const int i = blockIdx.x * 256 + threadIdx.x;
    if (i >= n4) return;
    const float4 v = ((const float4*)x)[i];
    const float f[4] = {v.x, v.y, v.z, v.w};
    unsigned short hh[4], ll[4];
#pragma unroll
    for (int j = 0; j < 4; j++) {
        const __nv_bfloat16 hb = __float2bfloat16(f[j]);
        const __nv_bfloat16 lb = __float2bfloat16(f[j] - __bfloat162float(hb));
        hh[j] = __bfloat16_as_ushort(hb);
        ll[j] = __bfloat16_as_ushort(lb);
    }
    ((uint2*)hi)[i] = *(const uint2*)hh;
    ((uint2*)lo)[i] = *(const uint2*)ll;
}

// ---------------------------------------------------------------------------
// Sinusoid rate + embedding (writes split bf16 directly)
// ---------------------------------------------------------------------------
__global__ void rate_kernel(float* __restrict__ rate)
{
    const int d = blockIdx.x * 256 + threadIdx.x;
    if (d >= DD) return;
    const double LN1E4 = 9.210340371976184;
    const int par = d & 1;
    const float r1 = (float)exp(-LN1E4 * (double)d   / 1024.0);
    const float r2 = (float)exp( LN1E4 * (double)par / 1024.0);
    rate[d] = r1 * r2;
}

__global__ void embed_split(const int* __restrict__ x,
                            const float* __restrict__ emb,
                            const float* __restrict__ rate,
                            __nv_bfloat16* __restrict__ oh,
                            __nv_bfloat16* __restrict__ ol)
{
    const int bs = blockIdx.x;
    const int s  = bs & (SS - 1);
    const int tok = x[bs];
    const float* e = emb + (size_t)tok * DD;
    for (int d = threadIdx.x; d < DD; d += blockDim.x) {
        const int par = d & 1;
        const float ph = (float)s * rate[d] + 1.5707964f * (float)par;
        const float v = e[d] * 32.0f + sinf(ph);
        const __nv_bfloat16 hb = __float2bfloat16(v);
        oh[(size_t)bs * DD + d] = hb;
        ol[(size_t)bs * DD + d] = __float2bfloat16(v - __bfloat162float(hb));
    }
}

// ---------------------------------------------------------------------------
// LayerNorm over last dim (1024); reads fp32, writes SPLIT bf16.
// ---------------------------------------------------------------------------
__global__ __launch_bounds__(256)
void ln_split(const float* __restrict__ xin, const float* __restrict__ g,
              const float* __restrict__ be,
              __nv_bfloat16* __restrict__ oh, __nv_bfloat16* __restrict__ ol)
{
    const int row = blockIdx.x;
    const float* p = xin + (size_t)row * DD;
    const int t = threadIdx.x;
    float v[4];
    float s = 0.f, s2 = 0.f;
#pragma unroll
    for (int c = 0; c < 4; c++) {
        v[c] = p[t + c * 256];
        s += v[c];
        s2 += v[c] * v[c];
    }
    __shared__ float sh1[8], sh2[8];
#pragma unroll
    for (int o = 16; o > 0; o >>= 1) {
        s  += __shfl_xor_sync(0xffffffffu, s,  o);
        s2 += __shfl_xor_sync(0xffffffffu, s2, o);
    }
    if ((t & 31) == 0) { sh1[t >> 5] = s; sh2[t >> 5] = s2; }
    __syncthreads();
    s = 0.f; s2 = 0.f;
#pragma unroll
    for (int w = 0; w < 8; w++) { s += sh1[w]; s2 += sh2[w]; }
    const float mu  = s  * (1.f / DD);
    const float var = s2 * (1.f / DD) - mu * mu;
    const float inv = rsqrtf(var + 1e-6f);
#pragma unroll
    for (int c = 0; c < 4; c++) {
        const int d = t + c * 256;
        const float o = (v[c] - mu) * inv * g[d] + be[d];
        const __nv_bfloat16 hb = __float2bfloat16(o);
        oh[(size_t)row * DD + d] = hb;
        ol[(size_t)row * DD + d] = __float2bfloat16(o - __bfloat162float(hb));
    }
}

// ---------------------------------------------------------------------------
// Host side
// ---------------------------------------------------------------------------
using bf16 = __nv_bfloat16;

template<int BN, int SKIP, bool KCAP, int OUT, bool RELU>
static void run_mma_s(cudaStream_t st,
                      const bf16* ah, const bf16* al, const bf16* bh, const bf16* bl,
                      const float* bias, float* C, bf16* Ch, bf16* Cl,
                      int M, int N, int K, int lda, int ldb, int ldc,
                      int batch, int zdiv,
                      long long sA1, long long sA2,
                      long long sB1, long long sB2,
                      long long sC1, long long sC2)
{
    constexpr int STG = 2 * 10240 + 2 * BN * 80;
    static bool init = false;
    if (!init) {
        cudaFuncSetAttribute(gemm_mma<BN, SKIP, KCAP, OUT, RELU>,
                             cudaFuncAttributeMaxDynamicSharedMemorySize, 2 * STG);
        init = true;
    }
    dim3 grid(N / BN, M / 128, batch);
    gemm_mma<BN, SKIP, KCAP, OUT, RELU><<<grid, 256, 2 * STG, st>>>(
        ah, al, bh, bl, bias, C, Ch, Cl, K, lda, ldb, ldc,
        zdiv, sA1, sA2, sB1, sB2, sC1, sC2);
}

extern "C" void kernel_launch(void* const* d_in, const int* in_sizes, int n_in,
                              void* d_out, int out_size)
{
    const int*   x   = (const int*)  d_in[0];
    const float* emb = (const float*)d_in[1];
    const float* Wq  = (const float*)d_in[2];
    const float* bq  = (const float*)d_in[3];
    const float* Wk  = (const float*)d_in[4];
    const float* bk  = (const float*)d_in[5];
    const float* Wv  = (const float*)d_in[6];
    const float* bv  = (const float*)d_in[7];
    const float* Wo  = (const float*)d_in[8];
    const float* bo  = (const float*)d_in[9];
    const float* W1  = (const float*)d_in[10];
    const float* b1  = (const float*)d_in[11];
    const float* W2  = (const float*)d_in[12];
    const float* b2  = (const float*)d_in[13];
    const float* g1  = (const float*)d_in[14];
    const float* be1 = (const float*)d_in[15];
    const float* g2  = (const float*)d_in[16];
    const float* be2 = (const float*)d_in[17];
    const float* E   = (const float*)d_in[18];
    const float* Wf  = (const float*)d_in[19];
    const float* bf  = (const float*)d_in[20];
    float* out = (float*)d_out;

    static cudaStream_t s1 = nullptr;
    static cudaEvent_t evFork = nullptr, evJoin = nullptr, evK = nullptr, evV = nullptr;
    if (!s1) {
        cudaStreamCreateWithFlags(&s1, cudaStreamNonBlocking);
        cudaEventCreateWithFlags(&evFork, cudaEventDisableTiming);
        cudaEventCreateWithFlags(&evJoin, cudaEventDisableTiming);
        cudaEventCreateWithFlags(&evK,    cudaEventDisableTiming);
        cudaEventCreateWithFlags(&evV,    cudaEventDisableTiming);
    }
    cudaStream_t s0 = 0;

    cudaFuncSetAttribute(av_gemm, cudaFuncAttributeMaxDynamicSharedMemorySize,
                         AV_SMEM);

    float *t1, *h2, *qe, *lg, *rate, *ps;
    cudaGetSymbolAddress((void**)&t1, g_t1);
    cudaGetSymbolAddress((void**)&h2, g_h2);
    cudaGetSymbolAddress((void**)&qe, g_qe);
    cudaGetSymbolAddress((void**)&lg, g_lg);
    cudaGetSymbolAddress((void**)&rate, g_rate);
    cudaGetSymbolAddress((void**)&ps, g_ps);

    bf16 *xh, *xl, *qkh, *qkl, *vth, *vtl, *ath, *atl, *ffh, *ffl, *eh, *el;
    cudaGetSymbolAddress((void**)&xh,  g_xh);  cudaGetSymbolAddress((void**)&xl,  g_xl);
    cudaGetSymbolAddress((void**)&qkh, g_qkh); cudaGetSymbolAddress((void**)&qkl, g_qkl);
    cudaGetSymbolAddress((void**)&vth, g_vth); cudaGetSymbolAddress((void**)&vtl, g_vtl);
    cudaGetSymbolAddress((void**)&ath, g_ath); cudaGetSymbolAddress((void**)&atl, g_atl);
    cudaGetSymbolAddress((void**)&ffh, g_ffh); cudaGetSymbolAddress((void**)&ffl, g_ffl);
    cudaGetSymbolAddress((void**)&eh,  g_eh);  cudaGetSymbolAddress((void**)&el,  g_el);

    bf16 *wqkh, *wqkl, *wvh, *wvl, *woh, *wol;
    bf16 *w1h, *w1l, *w2h, *w2l, *wfh, *wfl;
    cudaGetSymbolAddress((void**)&wqkh, g_wqk_h); cudaGetSymbolAddress((void**)&wqkl, g_wqk_l);
    cudaGetSymbolAddress((void**)&wvh, g_wv_h); cudaGetSymbolAddress((void**)&wvl, g_wv_l);
    cudaGetSymbolAddress((void**)&woh, g_wo_h); cudaGetSymbolAddress((void**)&wol, g_wo_l);
    cudaGetSymbolAddress((void**)&w1h, g_w1_h); cudaGetSymbolAddress((void**)&w1l, g_w1_l);
    cudaGetSymbolAddress((void**)&w2h, g_w2_h); cudaGetSymbolAddress((void**)&w2l, g_w2_l);
    cudaGetSymbolAddress((void**)&wfh, g_wf_h); cudaGetSymbolAddress((void**)&wfl, g_wf_l);

    const int M = BB * SS;  // 2048
    const long long sSD  = (long long)SS * DD;
    const long long sSQK = (long long)SS * QKW;
    const long long sHSS = (long long)HH * SS * SS;
    const long long sSSq = (long long)SS * SS;
    const long long sDS  = (long long)DD * SS;
    const long long wQKL = (long long)QKW * DD;

    // ---- setup: conversions on s0 || {rest, rate, embed} on s1
    cudaEventRecord(evFork, s0);
    cudaStreamWaitEvent(s1, evFork, 0);

    conv_w<<<dim3(DD / 64, DD / 64, LL), 256, 0, s0>>>(Wq, wqkh, wqkl, DD, DD, wQKL);
    conv_w<<<dim3(DD / 64, DD / 64, LL), 256, 0, s0>>>(Wk, wqkh + (size_t)DD * DD,
                                                       wqkl + (size_t)DD * DD, DD, DD, wQKL);
    conv_w<<<dim3(DD / 64, DD / 64, LL), 256, 0, s0>>>(Wv, wvh, wvl, DD, DD, (long long)DD * DD);

    conv_w<<<dim3(DD / 64, DD / 64, LL), 256, 0, s1>>>(Wo, woh, wol, DD, DD, (long long)DD * DD);
    conv_w<<<dim3(DF / 64, DD / 64, LL), 256, 0, s1>>>(W1, w1h, w1l, DD, DF, (long long)DF * DD);
    conv_w<<<dim3(DD / 64, DF / 64, LL), 256, 0, s1>>>(W2, w2h, w2l, DF, DD, (long long)DD * DF);
    conv_w<<<dim3(VV / 64, DD / 64, 1),  256, 0, s1>>>(Wf, wfh, wfl, DD, VV, (long long)VV * DD);
    split_act<<<(LL * SS * HD / 4 + 255) / 256, 256, 0, s1>>>(E, eh, el, LL * SS * HD / 4);
    rate_kernel<<<4, 256, 0, s1>>>(rate);
    embed_split<<<BB * SS, 256, 0, s1>>>(x, emb, rate, xh, xl);

    cudaEventRecord(evJoin, s1);
    cudaStreamWaitEvent(s0, evJoin, 0);

    for (int l = 0; l < LL; l++) {
        const size_t wdd = (size_t)l * DD * DD;
        const size_t wdf = (size_t)l * DF * DD;
        const bf16* ehl = eh + (size_t)l * SS * HD;
        const bf16* ell = el + (size_t)l * SS * HD;

        // fork: K-proj + V-proj on s1, Q-proj -> QE -> QK on s0
        cudaEventRecord(evFork, s0);
        cudaStreamWaitEvent(s1, evFork, 0);

        // Q projection (columns 0..1023 of qk buffer), BN=64 -> 256 CTAs
        run_mma_s<64, 0, false, 1, false>(s0, xh, xl, wqkh + (size_t)l * wQKL,
                                          wqkl + (size_t)l * wQKL, bq + l * DD,
                                          nullptr, qkh, qkl, M, DD, DD, DD, DD, QKW,
                                          1, 1, 0, 0, 0, 0, 0, 0);

        // K projection (columns 1024..2047) on s1, BN=64
        run_mma_s<64, 0, false, 1, false>(s1, xh, xl,
                                          wqkh + (size_t)l * wQKL + (size_t)DD * DD,
                                          wqkl + (size_t)l * wQKL + (size_t)DD * DD,
                                          bk + l * DD,
                                          nullptr, qkh + DD, qkl + DD,
                                          M, DD, DD, DD, DD, QKW,
                                          1, 1, 0, 0, 0, 0, 0, 0);
        cudaEventRecord(evK, s1);
        // V projection (split-transposed per batch) on s1
        run_mma_s<128, 0, false, 2, false>(s1, xh, xl, wvh + wdd, wvl + wdd, bv + l * DD,
                                           nullptr, vth, vtl, SS, DD, DD, DD, DD, SS,
                                           BB, 1, sSD, 0, 0, 0, sDS, 0);
        cudaEventRecord(evV, s1);

        // QE (anti-diagonal tiles only) on s0 -- needs q only
        run_mma_s<128, 1, false, 0, false>(s0, qkh, qkl, ehl, ell, nullptr, qe,
                                           nullptr, nullptr,
                                           SS, SS, HD, QKW, HD, SS, BB * HH, HH,
                                           sSQK, HD, 0, 0, sHSS, sSSq);

        // QK^T with fused Srel + masks + exp + sumexp partials (OUT=3)
        cudaStreamWaitEvent(s0, evK, 0);
        run_mma_s<128, 2, false, 3, false>(s0, qkh, qkl, qkh + DD, qkl + DD,
                                           (const float*)x, lg, (bf16*)qe, (bf16*)ps,
                                           SS, SS, HD, QKW, QKW, SS, BB * HH, HH,
                                           sSQK, HD, sSQK, HD, sHSS, sSSq);

        // attn = P @ v, inline invS
        cudaStreamWaitEvent(s0, evV, 0);
        av_gemm<<<dim3(1, SS / 128, BB * HH), 256, AV_SMEM, s0>>>(
            lg, ps, vth, vtl, ath, atl);

        // Wo + LN1 (BN=64 -> 256 CTAs)
        run_mma_s<64, 0, false, 0, false>(s0, ath, atl, woh + wdd, wol + wdd, bo + l * DD,
                                          t1, nullptr, nullptr, M, DD, DD, DD, DD, DD,
                                          1, 1, 0, 0, 0, 0, 0, 0);
        ln_split<<<BB * SS, 256, 0, s0>>>(t1, g1 + l * DD, be1 + l * DD, xh, xl);

        // FFN (W1 BN=64 -> 128 CTAs; W2 BN=64 -> 256 CTAs)
        run_mma_s<64, 0, false, 1, true>(s0, xh, xl, w1h + wdf, w1l + wdf, b1 + l * DF,
                                         nullptr, ffh, ffl, M, DF, DD, DD, DD, DF,
                                         1, 1, 0, 0, 0, 0, 0, 0);
        run_mma_s<64, 0, false, 0, false>(s0, ffh, ffl, w2h + wdf, w2l + wdf, b2 + l * DD,
                                          h2, nullptr, nullptr, M, DD, DF, DF, DF, DD,
                                          1, 1, 0, 0, 0, 0, 0, 0);
        ln_split<<<BB * SS, 256, 0, s0>>>(h2, g2 + l * DD, be2 + l * DD, xh, xl);
    }

    // final projection to vocab
    run_mma_s<64, 0, false, 0, false>(s0, xh, xl, wfh, wfl, bf, out, nullptr, nullptr,
                                      M, VV, DD, DD, DD, VV, 1, 1, 0, 0, 0, 0, 0, 0);
}

// round 16
// speedup vs baseline: 1.0188x; 1.0188x over previous
#include <cuda_runtime.h>
#include <cuda_bf16.h>
#include <math.h>
#include <stdint.h>

// ---------------------------------------------------------------------------
// Problem constants
// ---------------------------------------------------------------------------
constexpr int BB = 2;     // batch
constexpr int SS = 1024;  // seq len
constexpr int DD = 1024;  // model dim
constexpr int HH = 16;    // heads
constexpr int LL = 6;     // layers
constexpr int VV = 256;   // vocab
constexpr int HD = 64;    // head dim
constexpr int DF = 512;   // ffn dim
constexpr int QKW = 2048; // combined q|k width
constexpr float ATT_SCALE = 0.125f;  // 1/sqrt(64)

// ---------------------------------------------------------------------------
// Scratch (static device globals -- no allocations allowed)
// ---------------------------------------------------------------------------
__device__ float g_t1 [BB * SS * DD];                 // pre-LN fp32
__device__ float g_h2 [BB * SS * DD];                 // pre-LN fp32
__device__ float g_qe [(size_t)BB * HH * SS * SS];    // 134 MB
__device__ float g_lg [(size_t)BB * HH * SS * SS];    // exp(logits), 134 MB
__device__ float g_rate[DD];
__device__ float g_ps [(size_t)BB * HH * SS * 16];    // per-(row,tile,half) sumexp

// split activation buffers
__device__ __nv_bfloat16 g_xh [BB * SS * DD], g_xl [BB * SS * DD];  // layer in
__device__ __nv_bfloat16 g_qkh[BB * SS * QKW], g_qkl[BB * SS * QKW]; // q|k
__device__ __nv_bfloat16 g_vth[BB * DD * SS], g_vtl[BB * DD * SS];  // v^T per head
__device__ __nv_bfloat16 g_ath[BB * SS * DD], g_atl[BB * SS * DD];  // attn out
__device__ __nv_bfloat16 g_ffh[BB * SS * DF], g_ffl[BB * SS * DF];
__device__ __nv_bfloat16 g_eh [LL * SS * HD], g_el [LL * SS * HD];

// bf16 split weight buffers ([N, K] transposed, hi/lo)
__device__ __nv_bfloat16 g_wqk_h[LL * QKW * DD], g_wqk_l[LL * QKW * DD];
__device__ __nv_bfloat16 g_wv_h[LL * DD * DD],  g_wv_l[LL * DD * DD];
__device__ __nv_bfloat16 g_wo_h[LL * DD * DD],  g_wo_l[LL * DD * DD];
__device__ __nv_bfloat16 g_w1_h[LL * DF * DD],  g_w1_l[LL * DF * DD];
__device__ __nv_bfloat16 g_w2_h[LL * DD * DF],  g_w2_l[LL * DD * DF];
__device__ __nv_bfloat16 g_wf_h[VV * DD],       g_wf_l[VV * DD];

// ---------------------------------------------------------------------------
// PTX helpers (mma.sync / ldmatrix / cp.async -- standard ISA, sm_80+)
// ---------------------------------------------------------------------------
__device__ __forceinline__ uint32_t smem_u32(const void* p) {
    uint32_t a;
    asm("{ .reg .u64 t; cvta.to.shared.u64 t, %1; cvt.u32.u64 %0, t; }"
        : "=r"(a) : "l"(p));
    return a;
}
__device__ __forceinline__ void cpasync16(uint32_t s, const void* g) {
    asm volatile("cp.async.ca.shared.global [%0], [%1], 16;"
                 :: "r"(s), "l"(g) : "memory");
}
__device__ __forceinline__ void ldm_x4(uint32_t a, uint32_t r[4]) {
    asm volatile("ldmatrix.sync.aligned.m8n8.x4.shared.b16 {%0,%1,%2,%3}, [%4];"
                 : "=r"(r[0]), "=r"(r[1]), "=r"(r[2]), "=r"(r[3]) : "r"(a));
}
__device__ __forceinline__ void mma_bf16(float c[4], const uint32_t a[4],
                                         const uint32_t b[2]) {
    asm volatile("mma.sync.aligned.m16n8k16.row.col.f32.bf16.bf16.f32 "
                 "{%0,%1,%2,%3}, {%4,%5,%6,%7}, {%8,%9}, {%0,%1,%2,%3};"
                 : "+f"(c[0]), "+f"(c[1]), "+f"(c[2]), "+f"(c[3])
                 : "r"(a[0]), "r"(a[1]), "r"(a[2]), "r"(a[3]),
                   "r"(b[0]), "r"(b[1]));
}
__device__ __forceinline__ uint32_t pack_bf2(float a, float b) {
    __nv_bfloat162 t = __floats2bfloat162_rn(a, b);
    return *(uint32_t*)&t;
}
__device__ __forceinline__ float bf_hi(float v) {
    return __bfloat162float(__float2bfloat16(v));
}

// ---------------------------------------------------------------------------
// Unified batched split-bf16 HMMA GEMM.
// OUT: 0 fp32 C; 1 split bf16; 2 split bf16 transposed (smem staged);
//      3 attention-logit mode: v = (acc + qe_gather)*scale + pad_mask (or
//        -1e30 beyond causal); exp(v) written fp32 to C; per-(row,tile,half)
//        sum of exp(v) written to psum (Cl), qe via Ch, tokens x via bias.
// ---------------------------------------------------------------------------
template<int BN, int SKIP, bool KCAP, int OUT, bool RELU>
__global__ __launch_bounds__(256, 2)
void gemm_mma(const __nv_bfloat16* __restrict__ Ahi, const __nv_bfloat16* __restrict__ Alo,
              const __nv_bfloat16* __restrict__ Bhi, const __nv_bfloat16* __restrict__ Blo,
              const float* __restrict__ bias, float* __restrict__ C,
              __nv_bfloat16* __restrict__ Ch, __nv_bfloat16* __restrict__ Cl,
              int K, int lda, int ldb, int ldc, int zdiv,
              long long sA1, long long sA2,
              long long sB1, long long sB2,
              long long sC1, long long sC2)
{
    constexpr int ABY = 10240;            // 128 rows * 80B
    constexpr int BBY = BN * 80;
    constexpr int STG = 2 * ABY + 2 * BBY;
    constexpr int NT  = BN / 16;
    constexpr int BN2 = BN / 2;
    constexpr int TP  = 136;              // transpose-stage pitch (bf16 elems)

    const int m0 = blockIdx.y * 128;
    const int n0 = blockIdx.x * BN;
    if (SKIP == 1 && (m0 + n0 + 127 + BN - 1 < SS - 1)) return;
    if (SKIP == 2 && (n0 >= m0 + 128)) return;

    extern __shared__ char dynsmem[];
    const uint32_t sbase = smem_u32(dynsmem);
    const int tid  = threadIdx.x;
    const int lane = tid & 31;
    const int warp = tid >> 5;
    const int wm = warp & 3;
    const int wn = warp >> 2;

    const int z  = blockIdx.z;
    const int zb = z / zdiv;
    const int zh = z % zdiv;
    Ahi += (size_t)zb * sA1 + (size_t)zh * sA2;
    Alo += (size_t)zb * sA1 + (size_t)zh * sA2;
    Bhi += (size_t)zb * sB1 + (size_t)zh * sB2;
    Blo += (size_t)zb * sB1 + (size_t)zh * sB2;
    if (OUT == 0 || OUT == 3) C += (size_t)zb * sC1 + (size_t)zh * sC2;
    if (OUT == 1 || OUT == 2) { Ch += (size_t)zb * sC1 + (size_t)zh * sC2;
                                Cl += (size_t)zb * sC1 + (size_t)zh * sC2; }
    const float* qeB = (OUT == 3)
        ? ((const float*)Ch + (size_t)zb * sC1 + (size_t)zh * sC2) : nullptr;
    float* psB = (OUT == 3) ? ((float*)Cl + (size_t)z * SS * 16) : nullptr;
    const int* xB = (OUT == 3) ? ((const int*)bias + (size_t)zb * SS) : nullptr;

    float acc[2][NT][4];
#pragma unroll
    for (int mt = 0; mt < 2; ++mt)
#pragma unroll
        for (int nt = 0; nt < NT; ++nt)
#pragma unroll
            for (int r = 0; r < 4; ++r) acc[mt][nt][r] = 0.f;

    const int Keff = KCAP ? min(K, m0 + 128) : K;
    const int nch  = Keff >> 5;

    auto load_stage = [&](int c) {
        const int k0c = c << 5;
        const uint32_t sb = sbase + (c & 1) * STG;
#pragma unroll
        for (int i = 0; i < 2; ++i) {
            const int u = tid + i * 256;
            const int row = u >> 2, seg = u & 3;
            const uint32_t so = sb + row * 80 + seg * 16;
            const size_t ga = (size_t)(m0 + row) * lda + k0c + seg * 8;
            cpasync16(so,       Ahi + ga);
            cpasync16(so + ABY, Alo + ga);
        }
        constexpr int BU = (BN * 4) / 256;
#pragma unroll
        for (int i = 0; i < BU; ++i) {
            const int u = tid + i * 256;
            const int row = u >> 2, seg = u & 3;
            const uint32_t so = sb + 2 * ABY + row * 80 + seg * 16;
            const size_t gb = (size_t)(n0 + row) * ldb + k0c + seg * 8;
            cpasync16(so,       Bhi + gb);
            cpasync16(so + BBY, Blo + gb);
        }
        asm volatile("cp.async.commit_group;" ::: "memory");
    };

    load_stage(0);

    const int lr  = lane & 7;
    const int sel = lane >> 3;
    const int a_row_off = lr + ((sel & 1) << 3);
    const int a_k_off   = (sel >> 1) << 3;
    const int b_n_off   = lr + ((sel >> 1) << 3);
    const int b_k_off   = (sel & 1) << 3;

    for (int c = 0; c < nch; ++c) {
        if (c + 1 < nch) {
            load_stage(c + 1);
            asm volatile("cp.async.wait_group 1;" ::: "memory");
        } else {
            asm volatile("cp.async.wait_group 0;" ::: "memory");
        }
        __syncthreads();
        const uint32_t sb = sbase + (c & 1) * STG;

#pragma unroll
        for (int ks = 0; ks < 2; ++ks) {
            const int kk = ks << 4;
            uint32_t ah[2][4], al[2][4], bb[NT][2];
#pragma unroll
            for (int mt = 0; mt < 2; ++mt) {
                const int row = wm * 32 + mt * 16 + a_row_off;
                const uint32_t ad = sb + row * 80 + (kk + a_k_off) * 2;
                ldm_x4(ad, ah[mt]);
                ldm_x4(ad + ABY, al[mt]);
            }
#pragma unroll
            for (int p = 0; p < NT / 2; ++p) {
                const int n = wn * BN2 + p * 16 + b_n_off;
                uint32_t r[4];
                ldm_x4(sb + 2 * ABY + n * 80 + (kk + b_k_off) * 2, r);
                bb[2 * p][0]     = r[0]; bb[2 * p][1]     = r[1];
                bb[2 * p + 1][0] = r[2]; bb[2 * p + 1][1] = r[3];
            }
#pragma unroll
            for (int mt = 0; mt < 2; ++mt)
#pragma unroll
                for (int nt = 0; nt < NT; ++nt)
                    mma_bf16(acc[mt][nt], ah[mt], bb[nt]);
#pragma unroll
            for (int mt = 0; mt < 2; ++mt)
#pragma unroll
                for (int nt = 0; nt < NT; ++nt)
                    mma_bf16(acc[mt][nt], al[mt], bb[nt]);
#pragma unroll
            for (int p = 0; p < NT / 2; ++p) {
                const int n = wn * BN2 + p * 16 + b_n_off;
                uint32_t r[4];
                ldm_x4(sb + 2 * ABY + BBY + n * 80 + (kk + b_k_off) * 2, r);
                bb[2 * p][0]     = r[0]; bb[2 * p][1]     = r[1];
                bb[2 * p + 1][0] = r[2]; bb[2 * p + 1][1] = r[3];
            }
#pragma unroll
            for (int mt = 0; mt < 2; ++mt)
#pragma unroll
                for (int nt = 0; nt < NT; ++nt)
                    mma_bf16(acc[mt][nt], ah[mt], bb[nt]);
        }
        __syncthreads();
    }

    const int rbase = m0 + wm * 32 + (lane >> 2);
    const int cbase = n0 + wn * BN2 + 2 * (lane & 3);
    __nv_bfloat16* tsh = (__nv_bfloat16*)dynsmem;            // OUT==2 staging
    __nv_bfloat16* tsl = (__nv_bfloat16*)(dynsmem + (size_t)BN * TP * 2);
#pragma unroll
    for (int mt = 0; mt < 2; ++mt) {
        const int i0r = rbase + mt * 16;
        const int i1r = i0r + 8;
        float e0 = 0.f, e1 = 0.f;                            // OUT==3 sums
#pragma unroll
        for (int nt = 0; nt < NT; ++nt) {
            const int col = cbase + nt * 8;
            float b0v = 0.f, b1v = 0.f;
            if (OUT != 3 && bias) { b0v = bias[col]; b1v = bias[col + 1]; }
            float v0 = acc[mt][nt][0] + b0v;
            float v1 = acc[mt][nt][1] + b1v;
            float v2 = acc[mt][nt][2] + b0v;
            float v3 = acc[mt][nt][3] + b1v;
            if (RELU) {
                v0 = fmaxf(v0, 0.f); v1 = fmaxf(v1, 0.f);
                v2 = fmaxf(v2, 0.f); v3 = fmaxf(v3, 0.f);
            }
            if (OUT == 0) {
                *(float2*)&C[(size_t)i0r * ldc + col] = make_float2(v0, v1);
                *(float2*)&C[(size_t)i1r * ldc + col] = make_float2(v2, v3);
            } else if (OUT == 1) {
                const float h0 = bf_hi(v0), h1 = bf_hi(v1);
                const float h2 = bf_hi(v2), h3 = bf_hi(v3);
                *(uint32_t*)&Ch[(size_t)i0r * ldc + col] = pack_bf2(h0, h1);
                *(uint32_t*)&Ch[(size_t)i1r * ldc + col] = pack_bf2(h2, h3);
                *(uint32_t*)&Cl[(size_t)i0r * ldc + col] = pack_bf2(v0 - h0, v1 - h1);
                *(uint32_t*)&Cl[(size_t)i1r * ldc + col] = pack_bf2(v2 - h2, v3 - h3);
            } else if (OUT == 2) {
                const float vv[4] = {v0, v1, v2, v3};
#pragma unroll
                for (int e = 0; e < 4; ++e) {
                    const int cc = col - n0 + (e & 1);
                    const int rr = i0r - m0 + (e >> 1) * 8;
                    const __nv_bfloat16 hb = __float2bfloat16(vv[e]);
                    tsh[cc * TP + rr] = hb;
                    tsl[cc * TP + rr] =
                        __float2bfloat16(vv[e] - __bfloat162float(hb));
                }
            } else {  // OUT == 3: attention-logit epilogue, stores exp(v)
                const int j0 = col, j1 = col + 1;
                const float p0 = (xB[j0] == 0) ? -1e9f : 0.f;
                const float p1 = (xB[j1] == 0) ? -1e9f : 0.f;
                v0 = (j0 <= i0r)
                   ? (v0 + qeB[(size_t)i0r * SS + (SS - 1 - i0r) + j0]) * ATT_SCALE + p0
                   : -1e30f;
                v1 = (j1 <= i0r)
                   ? (v1 + qeB[(size_t)i0r * SS + (SS - 1 - i0r) + j1]) * ATT_SCALE + p1
                   : -1e30f;
                v2 = (j0 <= i1r)
                   ? (v2 + qeB[(size_t)i1r * SS + (SS - 1 - i1r) + j0]) * ATT_SCALE + p0
                   : -1e30f;
                v3 = (j1 <= i1r)
                   ? (v3 + qeB[(size_t)i1r * SS + (SS - 1 - i1r) + j1]) * ATT_SCALE + p1
                   : -1e30f;
                const float ex0 = __expf(v0), ex1 = __expf(v1);
                const float ex2 = __expf(v2), ex3 = __expf(v3);
                *(float2*)&C[(size_t)i0r * ldc + col] = make_float2(ex0, ex1);
                *(float2*)&C[(size_t)i1r * ldc + col] = make_float2(ex2, ex3);
                e0 += ex0 + ex1;
                e1 += ex2 + ex3;
            }
        }
        if (OUT == 3) {
            e0 += __shfl_xor_sync(0xffffffffu, e0, 1);
            e0 += __shfl_xor_sync(0xffffffffu, e0, 2);
            e1 += __shfl_xor_sync(0xffffffffu, e1, 1);
            e1 += __shfl_xor_sync(0xffffffffu, e1, 2);
            if ((lane & 3) == 0) {
                psB[(size_t)i0r * 16 + (n0 >> 7) * 2 + wn] = e0;
                psB[(size_t)i1r * 16 + (n0 >> 7) * 2 + wn] = e1;
            }
        }
    }
    if (OUT == 2) {
        __syncthreads();
#pragma unroll
        for (int p = 0; p < BN / 16; ++p) {
            const int idx = tid + p * 256;
            const int row = idx >> 4, seg = idx & 15;
            const uint4 vh = *(const uint4*)&tsh[row * TP + seg * 8];
            const uint4 vl = *(const uint4*)&tsl[row * TP + seg * 8];
            *(uint4*)&Ch[(size_t)(n0 + row) * ldc + m0 + seg * 8] = vh;
            *(uint4*)&Cl[(size_t)(n0 + row) * ldc + m0 + seg * 8] = vl;
        }
    }
}

// ---------------------------------------------------------------------------
// AV GEMM: attn = P @ v, reading stored exp-values directly; invS computed
// inline from psum partials. B = v^T (split bf16). K capped causally.
// ---------------------------------------------------------------------------
constexpr int AV_AP   = 36;                       // A pitch (floats)
constexpr int AV_ABY  = 128 * AV_AP * 4;          // 18432 B
constexpr int AV_BBY  = 64 * 80;                  // 5120 B
constexpr int AV_STG  = AV_ABY + 2 * AV_BBY;      // 28672
constexpr int AV_SMEM = 2 * AV_STG;               // 57344

__global__ __launch_bounds__(256, 2)
void av_gemm(const float* __restrict__ lg, const float* __restrict__ ps,
             const __nv_bfloat16* __restrict__ vth, const __nv_bfloat16* __restrict__ vtl,
             __nv_bfloat16* __restrict__ oh, __nv_bfloat16* __restrict__ ol)
{
    extern __shared__ char dynsmem[];
    const uint32_t sbase = smem_u32(dynsmem);
    float* Asf = (float*)dynsmem;
    const int tid  = threadIdx.x;
    const int lane = tid & 31;
    const int warp = tid >> 5;
    const int wm = warp & 3;
    const int wn = warp >> 2;
    const int m0 = blockIdx.y * 128;
    const int bh = blockIdx.z;
    const int b  = bh >> 4;
    const int h  = bh & 15;

    const float* A = lg + (size_t)bh * SS * SS;
    const __nv_bfloat16* Bh = vth + ((size_t)b * DD + h * HD) * SS;
    const __nv_bfloat16* Bl = vtl + ((size_t)b * DD + h * HD) * SS;

    // inline invS from psum partials (deterministic fixed order)
    const int rr0 = m0 + wm * 32 + (lane >> 2);
    float iv[4];
#pragma unroll
    for (int r = 0; r < 4; ++r) {
        const int row = rr0 + r * 8;
        const float* pp = ps + ((size_t)bh * SS + row) * 16;
        const int nt2 = ((row >> 7) + 1) * 2;
        float s = 0.f;
        for (int t = 0; t < nt2; ++t) s += pp[t];
        iv[r] = 1.f / s;
    }

    float acc[2][4][4];
#pragma unroll
    for (int mt = 0; mt < 2; ++mt)
#pragma unroll
        for (int nt = 0; nt < 4; ++nt)
#pragma unroll
            for (int r = 0; r < 4; ++r) acc[mt][nt][r] = 0.f;

    const int Keff = min(SS, m0 + 128);
    const int nch  = Keff >> 5;

    auto load_stage = [&](int c) {
        const int k0c = c << 5;
        const uint32_t sb = sbase + (c & 1) * AV_STG;
#pragma unroll
        for (int i = 0; i < 4; ++i) {
            const int u = tid + i * 256;
            const int row = u >> 3, seg = u & 7;
            cpasync16(sb + row * (AV_AP * 4) + seg * 16,
                      A + (size_t)(m0 + row) * SS + k0c + seg * 4);
        }
        {
            const int row = tid >> 2, seg = tid & 3;
            const uint32_t so = sb + AV_ABY + row * 80 + seg * 16;
            const size_t gb = (size_t)row * SS + k0c + seg * 8;
            cpasync16(so,          Bh + gb);
            cpasync16(so + AV_BBY, Bl + gb);
        }
        asm volatile("cp.async.commit_group;" ::: "memory");
    };

    load_stage(0);

    const int lr  = lane & 7;
    const int sel = lane >> 3;
    const int b_n_off = lr + ((sel >> 1) << 3);
    const int b_k_off = (sel & 1) << 3;

    for (int c = 0; c < nch; ++c) {
        if (c + 1 < nch) {
            load_stage(c + 1);
            asm volatile("cp.async.wait_group 1;" ::: "memory");
        } else {
            asm volatile("cp.async.wait_group 0;" ::: "memory");
        }
        __syncthreads();
        const float* Af = Asf + ((c & 1) ? AV_STG / 4 : 0);
        const uint32_t sbB = sbase + (c & 1) * AV_STG + AV_ABY;

#pragma unroll
        for (int ks = 0; ks < 2; ++ks) {
            const int kk = ks << 4;
            const int c0 = kk + (lane & 3) * 2;
            uint32_t aH[2][4], aL[2][4], bb[4][2];
#pragma unroll
            for (int mt = 0; mt < 2; ++mt) {
                const float* Ar = Af + (wm * 32 + mt * 16 + (lane >> 2)) * AV_AP;
                const float2 x00 = *(const float2*)(Ar + c0);
                const float2 x10 = *(const float2*)(Ar + 8 * AV_AP + c0);
                const float2 x01 = *(const float2*)(Ar + c0 + 8);
                const float2 x11 = *(const float2*)(Ar + 8 * AV_AP + c0 + 8);
                const float i0 = iv[mt * 2], i1 = iv[mt * 2 + 1];
                const float p0 = x00.x * i0, p1 = x00.y * i0;
                const float p2 = x10.x * i1, p3 = x10.y * i1;
                const float p4 = x01.x * i0, p5 = x01.y * i0;
                const float p6 = x11.x * i1, p7 = x11.y * i1;
                const float h0 = bf_hi(p0), h1 = bf_hi(p1), h2 = bf_hi(p2), h3 = bf_hi(p3);
                const float h4 = bf_hi(p4), h5 = bf_hi(p5), h6 = bf_hi(p6), h7 = bf_hi(p7);
                aH[mt][0] = pack_bf2(h0, h1); aH[mt][1] = pack_bf2(h2, h3);
                aH[mt][2] = pack_bf2(h4, h5); aH[mt][3] = pack_bf2(h6, h7);
                aL[mt][0] = pack_bf2(p0 - h0, p1 - h1);
                aL[mt][1] = pack_bf2(p2 - h2, p3 - h3);
                aL[mt][2] = pack_bf2(p4 - h4, p5 - h5);
                aL[mt][3] = pack_bf2(p6 - h6, p7 - h7);
            }
#pragma unroll
            for (int np = 0; np < 2; ++np) {
                const int n = wn * 32 + np * 16 + b_n_off;
                uint32_t r[4];
                ldm_x4(sbB + n * 80 + (kk + b_k_off) * 2, r);
                bb[2 * np][0]     = r[0]; bb[2 * np][1]     = r[1];
                bb[2 * np + 1][0] = r[2]; bb[2 * np + 1][1] = r[3];
            }
#pragma unroll
            for (int mt = 0; mt < 2; ++mt)
#pragma unroll
                for (int nt = 0; nt < 4; ++nt)
                    mma_bf16(acc[mt][nt], aH[mt], bb[nt]);
#pragma unroll
            for (int mt = 0; mt < 2; ++mt)
#pragma unroll
                for (int nt = 0; nt < 4; ++nt)
                    mma_bf16(acc[mt][nt], aL[mt], bb[nt]);
#pragma unroll
            for (int np = 0; np < 2; ++np) {
                const int n = wn * 32 + np * 16 + b_n_off;
                uint32_t r[4];
                ldm_x4(sbB + AV_BBY + n * 80 + (kk + b_k_off) * 2, r);
                bb[2 * np][0]     = r[0]; bb[2 * np][1]     = r[1];
                bb[2 * np + 1][0] = r[2]; bb[2 * np + 1][1] = r[3];
            }
#pragma unroll
            for (int mt = 0; mt < 2; ++mt)
#pragma unroll
                for (int nt = 0; nt < 4; ++nt)
                    mma_bf16(acc[mt][nt], aH[mt], bb[nt]);
        }
        __syncthreads();
    }

    __nv_bfloat16* Oh = oh + ((size_t)b * SS) * DD + h * HD;
    __nv_bfloat16* Ol = ol + ((size_t)b * SS) * DD + h * HD;
    const int cb = wn * 32 + 2 * (lane & 3);
#pragma unroll
    for (int mt = 0; mt < 2; ++mt) {
        const int i0r = rr0 + mt * 16;
        const int i1r = i0r + 8;
#pragma unroll
        for (int nt = 0; nt < 4; ++nt) {
            const int col = cb + nt * 8;
            const float v0 = acc[mt][nt][0], v1 = acc[mt][nt][1];
            const float v2 = acc[mt][nt][2], v3 = acc[mt][nt][3];
            const float h0 = bf_hi(v0), h1 = bf_hi(v1);
            const float h2 = bf_hi(v2), h3 = bf_hi(v3);
            *(uint32_t*)&Oh[(size_t)i0r * DD + col] = pack_bf2(h0, h1);
            *(uint32_t*)&Oh[(size_t)i1r * DD + col] = pack_bf2(h2, h3);
            *(uint32_t*)&Ol[(size_t)i0r * DD + col] = pack_bf2(v0 - h0, v1 - h1);
            *(uint32_t*)&Ol[(size_t)i1r * DD + col] = pack_bf2(v2 - h2, v3 - h3);
        }
    }
}

// ---------------------------------------------------------------------------
// Weight transpose + bf16 hi/lo split (64x64 tiles, packed stores)
// ---------------------------------------------------------------------------
__global__ __launch_bounds__(256)
void conv_w(const float* __restrict__ W, __nv_bfloat16* __restrict__ hi,
            __nv_bfloat16* __restrict__ lo, int K, int N, long long lstride)
{
    __shared__ float t[64][65];   // [n][k]
    const int l = blockIdx.z;
    W  += (size_t)l * K * N;
    hi += (size_t)l * lstride;
    lo += (size_t)l * lstride;
    const int k0 = blockIdx.y * 64, n0 = blockIdx.x * 64;
    const int tid = threadIdx.x;
    const int tc = tid & 31;
    const int tr = tid >> 5;
#pragma unroll
    for (int i = 0; i < 8; ++i) {
        const int kk = tr + i * 8;
        const float2 v = *(const float2*)&W[(size_t)(k0 + kk) * N + n0 + tc * 2];
        t[tc * 2][kk]     = v.x;
        t[tc * 2 + 1][kk] = v.y;
    }
    __syncthreads();
    const int kp = (tid & 31) * 2;
    const int nb = tid >> 5;
#pragma unroll
    for (int i = 0; i < 8; ++i) {
        const int n = nb + i * 8;
        const float a = t[n][kp], b = t[n][kp + 1];
        const float ha = bf_hi(a), hb = bf_hi(b);
        *(uint32_t*)&hi[(size_t)(n0 + n) * K + k0 + kp] = pack_bf2(ha, hb);
        *(uint32_t*)&lo[(size_t)(n0 + n) * K + k0 + kp] = pack_bf2(a - ha, b - hb);
    }
}

// elementwise hi/lo split (for E)
__global__ void split_act(const float* __restrict__ x, __nv_bfloat16* __restrict__ hi,
                          __nv_bfloat16* __restrict__ lo, int n4)
{
    const int i = blockIdx.x * 256 + threadIdx.x;
    if (i >= n4) return;
    const float4 v = ((const float4*)x)[i];
    const float f[4] = {v.x, v.y, v.z, v.w};
    unsigned short hh[4], ll[4];
#pragma unroll
    for (int j = 0; j < 4; j++) {
        const __nv_bfloat16 hb = __float2bfloat16(f[j]);
        const __nv_bfloat16 lb = __float2bfloat16(f[j] - __bfloat162float(hb));
        hh[j] = __bfloat16_as_ushort(hb);
        ll[j] = __bfloat16_as_ushort(lb);
    }
    ((uint2*)hi)[i] = *(const uint2*)hh;
    ((uint2*)lo)[i] = *(const uint2*)ll;
}

// ---------------------------------------------------------------------------
// Sinusoid rate + embedding (writes split bf16 directly)
// ---------------------------------------------------------------------------
__global__ void rate_kernel(float* __restrict__ rate)
{
    const int d = blockIdx.x * 256 + threadIdx.x;
    if (d >= DD) return;
    const double LN1E4 = 9.210340371976184;
    const int par = d & 1;
    const float r1 = (float)exp(-LN1E4 * (double)d   / 1024.0);
    const float r2 = (float)exp( LN1E4 * (double)par / 1024.0);
    rate[d] = r1 * r2;
}

__global__ void embed_split(const int* __restrict__ x,
                            const float* __restrict__ emb,
                            const float* __restrict__ rate,
                            __nv_bfloat16* __restrict__ oh,
                            __nv_bfloat16* __restrict__ ol)
{
    const int bs = blockIdx.x;
    const int s  = bs & (SS - 1);
    const int tok = x[bs];
    const float* e = emb + (size_t)tok * DD;
    for (int d = threadIdx.x; d < DD; d += blockDim.x) {
        const int par = d & 1;
        const float ph = (float)s * rate[d] + 1.5707964f * (float)par;
        const float v = e[d] * 32.0f + sinf(ph);
        const __nv_bfloat16 hb = __float2bfloat16(v);
        oh[(size_t)bs * DD + d] = hb;
        ol[(size_t)bs * DD + d] = __float2bfloat16(v - __bfloat162float(hb));
    }
}

// ---------------------------------------------------------------------------
// LayerNorm over last dim (1024); reads fp32, writes SPLIT bf16.
// ---------------------------------------------------------------------------
__global__ __launch_bounds__(256)
void ln_split(const float* __restrict__ xin, const float* __restrict__ g,
              const float* __restrict__ be,
              __nv_bfloat16* __restrict__ oh, __nv_bfloat16* __restrict__ ol)
{
    const int row = blockIdx.x;
    const float* p = xin + (size_t)row * DD;
    const int t = threadIdx.x;
    float v[4];
    float s = 0.f, s2 = 0.f;
#pragma unroll
    for (int c = 0; c < 4; c++) {
        v[c] = p[t + c * 256];
        s += v[c];
        s2 += v[c] * v[c];
    }
    __shared__ float sh1[8], sh2[8];
#pragma unroll
    for (int o = 16; o > 0; o >>= 1) {
        s  += __shfl_xor_sync(0xffffffffu, s,  o);
        s2 += __shfl_xor_sync(0xffffffffu, s2, o);
    }
    if ((t & 31) == 0) { sh1[t >> 5] = s; sh2[t >> 5] = s2; }
    __syncthreads();
    s = 0.f; s2 = 0.f;
#pragma unroll
    for (int w = 0; w < 8; w++) { s += sh1[w]; s2 += sh2[w]; }
    const float mu  = s  * (1.f / DD);
    const float var = s2 * (1.f / DD) - mu * mu;
    const float inv = rsqrtf(var + 1e-6f);
#pragma unroll
    for (int c = 0; c < 4; c++) {
        const int d = t + c * 256;
        const float o = (v[c] - mu) * inv * g[d] + be[d];
        const __nv_bfloat16 hb = __float2bfloat16(o);
        oh[(size_t)row * DD + d] = hb;
        ol[(size_t)row * DD + d] = __float2bfloat16(o - __bfloat162float(hb));
    }
}

// ---------------------------------------------------------------------------
// Host side
// ---------------------------------------------------------------------------
using bf16 = __nv_bfloat16;

template<int BN, int SKIP, bool KCAP, int OUT, bool RELU>
static void run_mma_s(cudaStream_t st,
                      const bf16* ah, const bf16* al, const bf16* bh, const bf16* bl,
                      const float* bias, float* C, bf16* Ch, bf16* Cl,
                      int M, int N, int K, int lda, int ldb, int ldc,
                      int batch, int zdiv,
                      long long sA1, long long sA2,
                      long long sB1, long long sB2,
                      long long sC1, long long sC2)
{
    constexpr int STG = 2 * 10240 + 2 * BN * 80;
    static bool init = false;
    if (!init) {
        cudaFuncSetAttribute(gemm_mma<BN, SKIP, KCAP, OUT, RELU>,
                             cudaFuncAttributeMaxDynamicSharedMemorySize, 2 * STG);
        init = true;
    }
    dim3 grid(N / BN, M / 128, batch);
    gemm_mma<BN, SKIP, KCAP, OUT, RELU><<<grid, 256, 2 * STG, st>>>(
        ah, al, bh, bl, bias, C, Ch, Cl, K, lda, ldb, ldc,
        zdiv, sA1, sA2, sB1, sB2, sC1, sC2);
}

extern "C" void kernel_launch(void* const* d_in, const int* in_sizes, int n_in,
                              void* d_out, int out_size)
{
    const int*   x   = (const int*)  d_in[0];
    const float* emb = (const float*)d_in[1];
    const float* Wq  = (const float*)d_in[2];
    const float* bq  = (const float*)d_in[3];
    const float* Wk  = (const float*)d_in[4];
    const float* bk  = (const float*)d_in[5];
    const float* Wv  = (const float*)d_in[6];
    const float* bv  = (const float*)d_in[7];
    const float* Wo  = (const float*)d_in[8];
    const float* bo  = (const float*)d_in[9];
    const float* W1  = (const float*)d_in[10];
    const float* b1  = (const float*)d_in[11];
    const float* W2  = (const float*)d_in[12];
    const float* b2  = (const float*)d_in[13];
    const float* g1  = (const float*)d_in[14];
    const float* be1 = (const float*)d_in[15];
    const float* g2  = (const float*)d_in[16];
    const float* be2 = (const float*)d_in[17];
    const float* E   = (const float*)d_in[18];
    const float* Wf  = (const float*)d_in[19];
    const float* bf  = (const float*)d_in[20];
    float* out = (float*)d_out;

    static cudaStream_t s1 = nullptr;
    static cudaEvent_t evFork = nullptr, evJoin = nullptr, evK = nullptr;
    static cudaEvent_t evV = nullptr, evQ = nullptr, evQE1 = nullptr;
    if (!s1) {
        cudaStreamCreateWithFlags(&s1, cudaStreamNonBlocking);
        cudaEventCreateWithFlags(&evFork, cudaEventDisableTiming);
        cudaEventCreateWithFlags(&evJoin, cudaEventDisableTiming);
        cudaEventCreateWithFlags(&evK,    cudaEventDisableTiming);
        cudaEventCreateWithFlags(&evV,    cudaEventDisableTiming);
        cudaEventCreateWithFlags(&evQ,    cudaEventDisableTiming);
        cudaEventCreateWithFlags(&evQE1,  cudaEventDisableTiming);
    }
    cudaStream_t s0 = 0;

    cudaFuncSetAttribute(av_gemm, cudaFuncAttributeMaxDynamicSharedMemorySize,
                         AV_SMEM);

    float *t1, *h2, *qe, *lg, *rate, *ps;
    cudaGetSymbolAddress((void**)&t1, g_t1);
    cudaGetSymbolAddress((void**)&h2, g_h2);
    cudaGetSymbolAddress((void**)&qe, g_qe);
    cudaGetSymbolAddress((void**)&lg, g_lg);
    cudaGetSymbolAddress((void**)&rate, g_rate);
    cudaGetSymbolAddress((void**)&ps, g_ps);

    bf16 *xh, *xl, *qkh, *qkl, *vth, *vtl, *ath, *atl, *ffh, *ffl, *eh, *el;
    cudaGetSymbolAddress((void**)&xh,  g_xh);  cudaGetSymbolAddress((void**)&xl,  g_xl);
    cudaGetSymbolAddress((void**)&qkh, g_qkh); cudaGetSymbolAddress((void**)&qkl, g_qkl);
    cudaGetSymbolAddress((void**)&vth, g_vth); cudaGetSymbolAddress((void**)&vtl, g_vtl);
    cudaGetSymbolAddress((void**)&ath, g_ath); cudaGetSymbolAddress((void**)&atl, g_atl);
    cudaGetSymbolAddress((void**)&ffh, g_ffh); cudaGetSymbolAddress((void**)&ffl, g_ffl);
    cudaGetSymbolAddress((void**)&eh,  g_eh);  cudaGetSymbolAddress((void**)&el,  g_el);

    bf16 *wqkh, *wqkl, *wvh, *wvl, *woh, *wol;
    bf16 *w1h, *w1l, *w2h, *w2l, *wfh, *wfl;
    cudaGetSymbolAddress((void**)&wqkh, g_wqk_h); cudaGetSymbolAddress((void**)&wqkl, g_wqk_l);
    cudaGetSymbolAddress((void**)&wvh, g_wv_h); cudaGetSymbolAddress((void**)&wvl, g_wv_l);
    cudaGetSymbolAddress((void**)&woh, g_wo_h); cudaGetSymbolAddress((void**)&wol, g_wo_l);
    cudaGetSymbolAddress((void**)&w1h, g_w1_h); cudaGetSymbolAddress((void**)&w1l, g_w1_l);
    cudaGetSymbolAddress((void**)&w2h, g_w2_h); cudaGetSymbolAddress((void**)&w2l, g_w2_l);
    cudaGetSymbolAddress((void**)&wfh, g_wf_h); cudaGetSymbolAddress((void**)&wfl, g_wf_l);

    const int M = BB * SS;  // 2048
    const long long sSD  = (long long)SS * DD;
    const long long sSQK = (long long)SS * QKW;
    const long long sHSS = (long long)HH * SS * SS;
    const long long sSSq = (long long)SS * SS;
    const long long sDS  = (long long)DD * SS;
    const long long wQKL = (long long)QKW * DD;

    // ---- setup: conversions on s0 || {rest, rate, embed} on s1
    cudaEventRecord(evFork, s0);
    cudaStreamWaitEvent(s1, evFork, 0);

    conv_w<<<dim3(DD / 64, DD / 64, LL), 256, 0, s0>>>(Wq, wqkh, wqkl, DD, DD, wQKL);
    conv_w<<<dim3(DD / 64, DD / 64, LL), 256, 0, s0>>>(Wk, wqkh + (size_t)DD * DD,
                                                       wqkl + (size_t)DD * DD, DD, DD, wQKL);
    conv_w<<<dim3(DD / 64, DD / 64, LL), 256, 0, s0>>>(Wv, wvh, wvl, DD, DD, (long long)DD * DD);

    conv_w<<<dim3(DD / 64, DD / 64, LL), 256, 0, s1>>>(Wo, woh, wol, DD, DD, (long long)DD * DD);
    conv_w<<<dim3(DF / 64, DD / 64, LL), 256, 0, s1>>>(W1, w1h, w1l, DD, DF, (long long)DF * DD);
    conv_w<<<dim3(DD / 64, DF / 64, LL), 256, 0, s1>>>(W2, w2h, w2l, DF, DD, (long long)DD * DF);
    conv_w<<<dim3(VV / 64, DD / 64, 1),  256, 0, s1>>>(Wf, wfh, wfl, DD, VV, (long long)VV * DD);
    split_act<<<(LL * SS * HD / 4 + 255) / 256, 256, 0, s1>>>(E, eh, el, LL * SS * HD / 4);
    rate_kernel<<<4, 256, 0, s1>>>(rate);
    embed_split<<<BB * SS, 256, 0, s1>>>(x, emb, rate, xh, xl);

    cudaEventRecord(evJoin, s1);
    cudaStreamWaitEvent(s0, evJoin, 0);

    for (int l = 0; l < LL; l++) {
        const size_t wdd = (size_t)l * DD * DD;
        const size_t wdf = (size_t)l * DF * DD;
        const bf16* ehl = eh + (size_t)l * SS * HD;
        const bf16* ell = el + (size_t)l * SS * HD;

        // fork: K-proj -> QE(b=1) -> V-proj on s1, Q-proj -> QE(b=0) -> QK on s0
        cudaEventRecord(evFork, s0);
        cudaStreamWaitEvent(s1, evFork, 0);

        // Q projection (columns 0..1023 of qk buffer), BN=128
        run_mma_s<128, 0, false, 1, false>(s0, xh, xl, wqkh + (size_t)l * wQKL,
                                           wqkl + (size_t)l * wQKL, bq + l * DD,
                                           nullptr, qkh, qkl, M, DD, DD, DD, DD, QKW,
                                           1, 1, 0, 0, 0, 0, 0, 0);
        cudaEventRecord(evQ, s0);

        // K projection (columns 1024..2047) on s1, BN=128
        run_mma_s<128, 0, false, 1, false>(s1, xh, xl,
                                           wqkh + (size_t)l * wQKL + (size_t)DD * DD,
                                           wqkl + (size_t)l * wQKL + (size_t)DD * DD,
                                           bk + l * DD,
                                           nullptr, qkh + DD, qkl + DD,
                                           M, DD, DD, DD, DD, QKW,
                                           1, 1, 0, 0, 0, 0, 0, 0);
        cudaEventRecord(evK, s1);

        // QE b=0 (bh 0..15) on s0
        run_mma_s<128, 1, false, 0, false>(s0, qkh, qkl, ehl, ell, nullptr, qe,
                                           nullptr, nullptr,
                                           SS, SS, HD, QKW, HD, SS, HH, HH,
                                           0, HD, 0, 0, 0, sSSq);

        // QE b=1 (bh 16..31) on s1 (needs Q done)
        cudaStreamWaitEvent(s1, evQ, 0);
        run_mma_s<128, 1, false, 0, false>(s1, qkh + sSQK, qkl + sSQK, ehl, ell,
                                           nullptr, qe + (size_t)HH * SS * SS,
                                           nullptr, nullptr,
                                           SS, SS, HD, QKW, HD, SS, HH, HH,
                                           0, HD, 0, 0, 0, sSSq);
        cudaEventRecord(evQE1, s1);

        // V projection (split-transposed per batch) on s1
        run_mma_s<128, 0, false, 2, false>(s1, xh, xl, wvh + wdd, wvl + wdd, bv + l * DD,
                                           nullptr, vth, vtl, SS, DD, DD, DD, DD, SS,
                                           BB, 1, sSD, 0, 0, 0, sDS, 0);
        cudaEventRecord(evV, s1);

        // QK^T with fused Srel + masks + exp + sumexp partials (OUT=3)
        cudaStreamWaitEvent(s0, evK, 0);
        cudaStreamWaitEvent(s0, evQE1, 0);
        run_mma_s<128, 2, false, 3, false>(s0, qkh, qkl, qkh + DD, qkl + DD,
                                           (const float*)x, lg, (bf16*)qe, (bf16*)ps,
                                           SS, SS, HD, QKW, QKW, SS, BB * HH, HH,
                                           sSQK, HD, sSQK, HD, sHSS, sSSq);

        // attn = P @ v, inline invS
        cudaStreamWaitEvent(s0, evV, 0);
        av_gemm<<<dim3(1, SS / 128, BB * HH), 256, AV_SMEM, s0>>>(
            lg, ps, vth, vtl, ath, atl);

        // Wo + LN1 (BN=128)
        run_mma_s<128, 0, false, 0, false>(s0, ath, atl, woh + wdd, wol + wdd, bo + l * DD,
                                           t1, nullptr, nullptr, M, DD, DD, DD, DD, DD,
                                           1, 1, 0, 0, 0, 0, 0, 0);
        ln_split<<<BB * SS, 256, 0, s0>>>(t1, g1 + l * DD, be1 + l * DD, xh, xl);

        // FFN (W1 BN=64; W2 BN=128)
        run_mma_s<64, 0, false, 1, true>(s0, xh, xl, w1h + wdf, w1l + wdf, b1 + l * DF,
                                         nullptr, ffh, ffl, M, DF, DD, DD, DD, DF,
                                         1, 1, 0, 0, 0, 0, 0, 0);
        run_mma_s<128, 0, false, 0, false>(s0, ffh, ffl, w2h + wdf, w2l + wdf, b2 + l * DD,
                                           h2, nullptr, nullptr, M, DD, DF, DF, DF, DD,
                                           1, 1, 0, 0, 0, 0, 0, 0);
        ln_split<<<BB * SS, 256, 0, s0>>>(h2, g2 + l * DD, be2 + l * DD, xh, xl);
    }

    // final projection to vocab
    run_mma_s<64, 0, false, 0, false>(s0, xh, xl, wfh, wfl, bf, out, nullptr, nullptr,
                                      M, VV, DD, DD, DD, VV, 1, 1, 0, 0, 0, 0, 0, 0);
}

// round 17
// speedup vs baseline: 1.0323x; 1.0133x over previous
#include <cuda_runtime.h>
#include <cuda_bf16.h>
#include <math.h>
#include <stdint.h>

// ---------------------------------------------------------------------------
// Problem constants
// ---------------------------------------------------------------------------
constexpr int BB = 2;     // batch
constexpr int SS = 1024;  // seq len
constexpr int DD = 1024;  // model dim
constexpr int HH = 16;    // heads
constexpr int LL = 6;     // layers
constexpr int VV = 256;   // vocab
constexpr int HD = 64;    // head dim
constexpr int DF = 512;   // ffn dim
constexpr int QKW = 2048; // combined q|k width
constexpr float ATT_SCALE = 0.125f;  // 1/sqrt(64)

// ---------------------------------------------------------------------------
// Scratch (static device globals -- no allocations allowed)
// ---------------------------------------------------------------------------
__device__ float g_t1 [BB * SS * DD];                 // pre-LN fp32
__device__ float g_h2 [BB * SS * DD];                 // pre-LN fp32
__device__ float g_qe [(size_t)BB * HH * SS * SS];    // 134 MB
__device__ float g_lg [(size_t)BB * HH * SS * SS];    // exp(logits), 134 MB
__device__ float g_rate[DD];
__device__ float g_ps [(size_t)BB * HH * SS * 16];    // per-(row,tile,half) sumexp

// split activation buffers
__device__ __nv_bfloat16 g_xh [BB * SS * DD], g_xl [BB * SS * DD];  // layer in
__device__ __nv_bfloat16 g_qkh[BB * SS * QKW], g_qkl[BB * SS * QKW]; // q|k
__device__ __nv_bfloat16 g_vth[BB * DD * SS], g_vtl[BB * DD * SS];  // v^T per head
__device__ __nv_bfloat16 g_ath[BB * SS * DD], g_atl[BB * SS * DD];  // attn out
__device__ __nv_bfloat16 g_ffh[BB * SS * DF], g_ffl[BB * SS * DF];
__device__ __nv_bfloat16 g_eh [LL * SS * HD], g_el [LL * SS * HD];

// bf16 split weight buffers ([N, K] transposed, hi/lo)
__device__ __nv_bfloat16 g_wqk_h[LL * QKW * DD], g_wqk_l[LL * QKW * DD];
__device__ __nv_bfloat16 g_wv_h[LL * DD * DD],  g_wv_l[LL * DD * DD];
__device__ __nv_bfloat16 g_wo_h[LL * DD * DD],  g_wo_l[LL * DD * DD];
__device__ __nv_bfloat16 g_w1_h[LL * DF * DD],  g_w1_l[LL * DF * DD];
__device__ __nv_bfloat16 g_w2_h[LL * DD * DF],  g_w2_l[LL * DD * DF];
__device__ __nv_bfloat16 g_wf_h[VV * DD],       g_wf_l[VV * DD];

// ---------------------------------------------------------------------------
// PTX helpers (mma.sync / ldmatrix / cp.async -- standard ISA, sm_80+)
// ---------------------------------------------------------------------------
__device__ __forceinline__ uint32_t smem_u32(const void* p) {
    uint32_t a;
    asm("{ .reg .u64 t; cvta.to.shared.u64 t, %1; cvt.u32.u64 %0, t; }"
        : "=r"(a) : "l"(p));
    return a;
}
__device__ __forceinline__ void cpasync16(uint32_t s, const void* g) {
    asm volatile("cp.async.ca.shared.global [%0], [%1], 16;"
                 :: "r"(s), "l"(g) : "memory");
}
__device__ __forceinline__ void ldm_x4(uint32_t a, uint32_t r[4]) {
    asm volatile("ldmatrix.sync.aligned.m8n8.x4.shared.b16 {%0,%1,%2,%3}, [%4];"
                 : "=r"(r[0]), "=r"(r[1]), "=r"(r[2]), "=r"(r[3]) : "r"(a));
}
__device__ __forceinline__ void mma_bf16(float c[4], const uint32_t a[4],
                                         const uint32_t b[2]) {
    asm volatile("mma.sync.aligned.m16n8k16.row.col.f32.bf16.bf16.f32 "
                 "{%0,%1,%2,%3}, {%4,%5,%6,%7}, {%8,%9}, {%0,%1,%2,%3};"
                 : "+f"(c[0]), "+f"(c[1]), "+f"(c[2]), "+f"(c[3])
                 : "r"(a[0]), "r"(a[1]), "r"(a[2]), "r"(a[3]),
                   "r"(b[0]), "r"(b[1]));
}
__device__ __forceinline__ uint32_t pack_bf2(float a, float b) {
    __nv_bfloat162 t = __floats2bfloat162_rn(a, b);
    return *(uint32_t*)&t;
}
__device__ __forceinline__ float bf_hi(float v) {
    return __bfloat162float(__float2bfloat16(v));
}

// ---------------------------------------------------------------------------
// Unified batched split-bf16 HMMA GEMM.
// OUT: 0 fp32 C; 1 split bf16; 2 split bf16 transposed (smem staged);
//      3 attention-logit mode: v = (acc + qe_gather)*scale + pad_mask (or
//        -1e30 beyond causal); exp(v) written fp32 to C; per-(row,tile,half)
//        sum of exp(v) written to psum (Cl), qe via Ch, tokens x via bias.
// SKIP==2 (causal) reverses the m-tile order so heavy tiles launch first.
// ---------------------------------------------------------------------------
template<int BN, int SKIP, bool KCAP, int OUT, bool RELU>
__global__ __launch_bounds__(256, 2)
void gemm_mma(const __nv_bfloat16* __restrict__ Ahi, const __nv_bfloat16* __restrict__ Alo,
              const __nv_bfloat16* __restrict__ Bhi, const __nv_bfloat16* __restrict__ Blo,
              const float* __restrict__ bias, float* __restrict__ C,
              __nv_bfloat16* __restrict__ Ch, __nv_bfloat16* __restrict__ Cl,
              int K, int lda, int ldb, int ldc, int zdiv,
              long long sA1, long long sA2,
              long long sB1, long long sB2,
              long long sC1, long long sC2)
{
    constexpr int ABY = 10240;            // 128 rows * 80B
    constexpr int BBY = BN * 80;
    constexpr int STG = 2 * ABY + 2 * BBY;
    constexpr int NT  = BN / 16;
    constexpr int BN2 = BN / 2;
    constexpr int TP  = 136;              // transpose-stage pitch (bf16 elems)

    const int my = (SKIP == 2) ? (gridDim.y - 1 - blockIdx.y) : blockIdx.y;
    const int m0 = my * 128;
    const int n0 = blockIdx.x * BN;
    if (SKIP == 1 && (m0 + n0 + 127 + BN - 1 < SS - 1)) return;
    if (SKIP == 2 && (n0 >= m0 + 128)) return;

    extern __shared__ char dynsmem[];
    const uint32_t sbase = smem_u32(dynsmem);
    const int tid  = threadIdx.x;
    const int lane = tid & 31;
    const int warp = tid >> 5;
    const int wm = warp & 3;
    const int wn = warp >> 2;

    const int z  = blockIdx.z;
    const int zb = z / zdiv;
    const int zh = z % zdiv;
    Ahi += (size_t)zb * sA1 + (size_t)zh * sA2;
    Alo += (size_t)zb * sA1 + (size_t)zh * sA2;
    Bhi += (size_t)zb * sB1 + (size_t)zh * sB2;
    Blo += (size_t)zb * sB1 + (size_t)zh * sB2;
    if (OUT == 0 || OUT == 3) C += (size_t)zb * sC1 + (size_t)zh * sC2;
    if (OUT == 1 || OUT == 2) { Ch += (size_t)zb * sC1 + (size_t)zh * sC2;
                                Cl += (size_t)zb * sC1 + (size_t)zh * sC2; }
    const float* qeB = (OUT == 3)
        ? ((const float*)Ch + (size_t)zb * sC1 + (size_t)zh * sC2) : nullptr;
    float* psB = (OUT == 3) ? ((float*)Cl + (size_t)z * SS * 16) : nullptr;
    const int* xB = (OUT == 3) ? ((const int*)bias + (size_t)zb * SS) : nullptr;

    float acc[2][NT][4];
#pragma unroll
    for (int mt = 0; mt < 2; ++mt)
#pragma unroll
        for (int nt = 0; nt < NT; ++nt)
#pragma unroll
            for (int r = 0; r < 4; ++r) acc[mt][nt][r] = 0.f;

    const int Keff = KCAP ? min(K, m0 + 128) : K;
    const int nch  = Keff >> 5;

    auto load_stage = [&](int c) {
        const int k0c = c << 5;
        const uint32_t sb = sbase + (c & 1) * STG;
#pragma unroll
        for (int i = 0; i < 2; ++i) {
            const int u = tid + i * 256;
            const int row = u >> 2, seg = u & 3;
            const uint32_t so = sb + row * 80 + seg * 16;
            const size_t ga = (size_t)(m0 + row) * lda + k0c + seg * 8;
            cpasync16(so,       Ahi + ga);
            cpasync16(so + ABY, Alo + ga);
        }
        constexpr int BU = (BN * 4) / 256;
#pragma unroll
        for (int i = 0; i < BU; ++i) {
            const int u = tid + i * 256;
            const int row = u >> 2, seg = u & 3;
            const uint32_t so = sb + 2 * ABY + row * 80 + seg * 16;
            const size_t gb = (size_t)(n0 + row) * ldb + k0c + seg * 8;
            cpasync16(so,       Bhi + gb);
            cpasync16(so + BBY, Blo + gb);
        }
        asm volatile("cp.async.commit_group;" ::: "memory");
    };

    load_stage(0);

    const int lr  = lane & 7;
    const int sel = lane >> 3;
    const int a_row_off = lr + ((sel & 1) << 3);
    const int a_k_off   = (sel >> 1) << 3;
    const int b_n_off   = lr + ((sel >> 1) << 3);
    const int b_k_off   = (sel & 1) << 3;

    for (int c = 0; c < nch; ++c) {
        if (c + 1 < nch) {
            load_stage(c + 1);
            asm volatile("cp.async.wait_group 1;" ::: "memory");
        } else {
            asm volatile("cp.async.wait_group 0;" ::: "memory");
        }
        __syncthreads();
        const uint32_t sb = sbase + (c & 1) * STG;

#pragma unroll
        for (int ks = 0; ks < 2; ++ks) {
            const int kk = ks << 4;
            uint32_t ah[2][4], al[2][4], bb[NT][2];
#pragma unroll
            for (int mt = 0; mt < 2; ++mt) {
                const int row = wm * 32 + mt * 16 + a_row_off;
                const uint32_t ad = sb + row * 80 + (kk + a_k_off) * 2;
                ldm_x4(ad, ah[mt]);
                ldm_x4(ad + ABY, al[mt]);
            }
#pragma unroll
            for (int p = 0; p < NT / 2; ++p) {
                const int n = wn * BN2 + p * 16 + b_n_off;
                uint32_t r[4];
                ldm_x4(sb + 2 * ABY + n * 80 + (kk + b_k_off) * 2, r);
                bb[2 * p][0]     = r[0]; bb[2 * p][1]     = r[1];
                bb[2 * p + 1][0] = r[2]; bb[2 * p + 1][1] = r[3];
            }
#pragma unroll
            for (int mt = 0; mt < 2; ++mt)
#pragma unroll
                for (int nt = 0; nt < NT; ++nt)
                    mma_bf16(acc[mt][nt], ah[mt], bb[nt]);
#pragma unroll
            for (int mt = 0; mt < 2; ++mt)
#pragma unroll
                for (int nt = 0; nt < NT; ++nt)
                    mma_bf16(acc[mt][nt], al[mt], bb[nt]);
#pragma unroll
            for (int p = 0; p < NT / 2; ++p) {
                const int n = wn * BN2 + p * 16 + b_n_off;
                uint32_t r[4];
                ldm_x4(sb + 2 * ABY + BBY + n * 80 + (kk + b_k_off) * 2, r);
                bb[2 * p][0]     = r[0]; bb[2 * p][1]     = r[1];
                bb[2 * p + 1][0] = r[2]; bb[2 * p + 1][1] = r[3];
            }
#pragma unroll
            for (int mt = 0; mt < 2; ++mt)
#pragma unroll
                for (int nt = 0; nt < NT; ++nt)
                    mma_bf16(acc[mt][nt], ah[mt], bb[nt]);
        }
        __syncthreads();
    }

    const int rbase = m0 + wm * 32 + (lane >> 2);
    const int cbase = n0 + wn * BN2 + 2 * (lane & 3);
    __nv_bfloat16* tsh = (__nv_bfloat16*)dynsmem;            // OUT==2 staging
    __nv_bfloat16* tsl = (__nv_bfloat16*)(dynsmem + (size_t)BN * TP * 2);
#pragma unroll
    for (int mt = 0; mt < 2; ++mt) {
        const int i0r = rbase + mt * 16;
        const int i1r = i0r + 8;
        float e0 = 0.f, e1 = 0.f;                            // OUT==3 sums
#pragma unroll
        for (int nt = 0; nt < NT; ++nt) {
            const int col = cbase + nt * 8;
            float b0v = 0.f, b1v = 0.f;
            if (OUT != 3 && bias) { b0v = bias[col]; b1v = bias[col + 1]; }
            float v0 = acc[mt][nt][0] + b0v;
            float v1 = acc[mt][nt][1] + b1v;
            float v2 = acc[mt][nt][2] + b0v;
            float v3 = acc[mt][nt][3] + b1v;
            if (RELU) {
                v0 = fmaxf(v0, 0.f); v1 = fmaxf(v1, 0.f);
                v2 = fmaxf(v2, 0.f); v3 = fmaxf(v3, 0.f);
            }
            if (OUT == 0) {
                *(float2*)&C[(size_t)i0r * ldc + col] = make_float2(v0, v1);
                *(float2*)&C[(size_t)i1r * ldc + col] = make_float2(v2, v3);
            } else if (OUT == 1) {
                const float h0 = bf_hi(v0), h1 = bf_hi(v1);
                const float h2 = bf_hi(v2), h3 = bf_hi(v3);
                *(uint32_t*)&Ch[(size_t)i0r * ldc + col] = pack_bf2(h0, h1);
                *(uint32_t*)&Ch[(size_t)i1r * ldc + col] = pack_bf2(h2, h3);
                *(uint32_t*)&Cl[(size_t)i0r * ldc + col] = pack_bf2(v0 - h0, v1 - h1);
                *(uint32_t*)&Cl[(size_t)i1r * ldc + col] = pack_bf2(v2 - h2, v3 - h3);
            } else if (OUT == 2) {
                const float vv[4] = {v0, v1, v2, v3};
#pragma unroll
                for (int e = 0; e < 4; ++e) {
                    const int cc = col - n0 + (e & 1);
                    const int rr = i0r - m0 + (e >> 1) * 8;
                    const __nv_bfloat16 hb = __float2bfloat16(vv[e]);
                    tsh[cc * TP + rr] = hb;
                    tsl[cc * TP + rr] =
                        __float2bfloat16(vv[e] - __bfloat162float(hb));
                }
            } else {  // OUT == 3: attention-logit epilogue, stores exp(v)
                const int j0 = col, j1 = col + 1;
                const float p0 = (xB[j0] == 0) ? -1e9f : 0.f;
                const float p1 = (xB[j1] == 0) ? -1e9f : 0.f;
                v0 = (j0 <= i0r)
                   ? (v0 + qeB[(size_t)i0r * SS + (SS - 1 - i0r) + j0]) * ATT_SCALE + p0
                   : -1e30f;
                v1 = (j1 <= i0r)
                   ? (v1 + qeB[(size_t)i0r * SS + (SS - 1 - i0r) + j1]) * ATT_SCALE + p1
                   : -1e30f;
                v2 = (j0 <= i1r)
                   ? (v2 + qeB[(size_t)i1r * SS + (SS - 1 - i1r) + j0]) * ATT_SCALE + p0
                   : -1e30f;
                v3 = (j1 <= i1r)
                   ? (v3 + qeB[(size_t)i1r * SS + (SS - 1 - i1r) + j1]) * ATT_SCALE + p1
                   : -1e30f;
                const float ex0 = __expf(v0), ex1 = __expf(v1);
                const float ex2 = __expf(v2), ex3 = __expf(v3);
                *(float2*)&C[(size_t)i0r * ldc + col] = make_float2(ex0, ex1);
                *(float2*)&C[(size_t)i1r * ldc + col] = make_float2(ex2, ex3);
                e0 += ex0 + ex1;
                e1 += ex2 + ex3;
            }
        }
        if (OUT == 3) {
            e0 += __shfl_xor_sync(0xffffffffu, e0, 1);
            e0 += __shfl_xor_sync(0xffffffffu, e0, 2);
            e1 += __shfl_xor_sync(0xffffffffu, e1, 1);
            e1 += __shfl_xor_sync(0xffffffffu, e1, 2);
            if ((lane & 3) == 0) {
                psB[(size_t)i0r * 16 + (n0 >> 7) * 2 + wn] = e0;
                psB[(size_t)i1r * 16 + (n0 >> 7) * 2 + wn] = e1;
            }
        }
    }
    if (OUT == 2) {
        __syncthreads();
#pragma unroll
        for (int p = 0; p < BN / 16; ++p) {
            const int idx = tid + p * 256;
            const int row = idx >> 4, seg = idx & 15;
            const uint4 vh = *(const uint4*)&tsh[row * TP + seg * 8];
            const uint4 vl = *(const uint4*)&tsl[row * TP + seg * 8];
            *(uint4*)&Ch[(size_t)(n0 + row) * ldc + m0 + seg * 8] = vh;
            *(uint4*)&Cl[(size_t)(n0 + row) * ldc + m0 + seg * 8] = vl;
        }
    }
}

// ---------------------------------------------------------------------------
// AV GEMM: attn = P @ v, reading stored exp-values directly; invS computed
// inline from psum partials. B = v^T (split bf16). K capped causally.
// Heavy m-tiles scheduled first (reversed blockIdx.y).
// ---------------------------------------------------------------------------
constexpr int AV_AP   = 36;                       // A pitch (floats)
constexpr int AV_ABY  = 128 * AV_AP * 4;          // 18432 B
constexpr int AV_BBY  = 64 * 80;                  // 5120 B
constexpr int AV_STG  = AV_ABY + 2 * AV_BBY;      // 28672
constexpr int AV_SMEM = 2 * AV_STG;               // 57344

__global__ __launch_bounds__(256, 2)
void av_gemm(const float* __restrict__ lg, const float* __restrict__ ps,
             const __nv_bfloat16* __restrict__ vth, const __nv_bfloat16* __restrict__ vtl,
             __nv_bfloat16* __restrict__ oh, __nv_bfloat16* __restrict__ ol)
{
    extern __shared__ char dynsmem[];
    const uint32_t sbase = smem_u32(dynsmem);
    float* Asf = (float*)dynsmem;
    const int tid  = threadIdx.x;
    const int lane = tid & 31;
    const int warp = tid >> 5;
    const int wm = warp & 3;
    const int wn = warp >> 2;
    const int m0 = (gridDim.y - 1 - blockIdx.y) * 128;   // heavy first
    const int bh = blockIdx.z;
    const int b  = bh >> 4;
    const int h  = bh & 15;

    const float* A = lg + (size_t)bh * SS * SS;
    const __nv_bfloat16* Bh = vth + ((size_t)b * DD + h * HD) * SS;
    const __nv_bfloat16* Bl = vtl + ((size_t)b * DD + h * HD) * SS;

    // inline invS from psum partials (deterministic fixed order)
    const int rr0 = m0 + wm * 32 + (lane >> 2);
    float iv[4];
#pragma unroll
    for (int r = 0; r < 4; ++r) {
        const int row = rr0 + r * 8;
        const float* pp = ps + ((size_t)bh * SS + row) * 16;
        const int nt2 = ((row >> 7) + 1) * 2;
        float s = 0.f;
        for (int t = 0; t < nt2; ++t) s += pp[t];
        iv[r] = 1.f / s;
    }

    float acc[2][4][4];
#pragma unroll
    for (int mt = 0; mt < 2; ++mt)
#pragma unroll
        for (int nt = 0; nt < 4; ++nt)
#pragma unroll
            for (int r = 0; r < 4; ++r) acc[mt][nt][r] = 0.f;

    const int Keff = min(SS, m0 + 128);
    const int nch  = Keff >> 5;

    auto load_stage = [&](int c) {
        const int k0c = c << 5;
        const uint32_t sb = sbase + (c & 1) * AV_STG;
#pragma unroll
        for (int i = 0; i < 4; ++i) {
            const int u = tid + i * 256;
            const int row = u >> 3, seg = u & 7;
            cpasync16(sb + row * (AV_AP * 4) + seg * 16,
                      A + (size_t)(m0 + row) * SS + k0c + seg * 4);
        }
        {
            const int row = tid >> 2, seg = tid & 3;
            const uint32_t so = sb + AV_ABY + row * 80 + seg * 16;
            const size_t gb = (size_t)row * SS + k0c + seg * 8;
            cpasync16(so,          Bh + gb);
            cpasync16(so + AV_BBY, Bl + gb);
        }
        asm volatile("cp.async.commit_group;" ::: "memory");
    };

    load_stage(0);

    const int lr  = lane & 7;
    const int sel = lane >> 3;
    const int b_n_off = lr + ((sel >> 1) << 3);
    const int b_k_off = (sel & 1) << 3;

    for (int c = 0; c < nch; ++c) {
        if (c + 1 < nch) {
            load_stage(c + 1);
            asm volatile("cp.async.wait_group 1;" ::: "memory");
        } else {
            asm volatile("cp.async.wait_group 0;" ::: "memory");
        }
        __syncthreads();
        const float* Af = Asf + ((c & 1) ? AV_STG / 4 : 0);
        const uint32_t sbB = sbase + (c & 1) * AV_STG + AV_ABY;

#pragma unroll
        for (int ks = 0; ks < 2; ++ks) {
            const int kk = ks << 4;
            const int c0 = kk + (lane & 3) * 2;
            uint32_t aH[2][4], aL[2][4], bb[4][2];
#pragma unroll
            for (int mt = 0; mt < 2; ++mt) {
                const float* Ar = Af + (wm * 32 + mt * 16 + (lane >> 2)) * AV_AP;
                const float2 x00 = *(const float2*)(Ar + c0);
                const float2 x10 = *(const float2*)(Ar + 8 * AV_AP + c0);
                const float2 x01 = *(const float2*)(Ar + c0 + 8);
                const float2 x11 = *(const float2*)(Ar + 8 * AV_AP + c0 + 8);
                const float i0 = iv[mt * 2], i1 = iv[mt * 2 + 1];
                const float p0 = x00.x * i0, p1 = x00.y * i0;
                const float p2 = x10.x * i1, p3 = x10.y * i1;
                const float p4 = x01.x * i0, p5 = x01.y * i0;
                const float p6 = x11.x * i1, p7 = x11.y * i1;
                const float h0 = bf_hi(p0), h1 = bf_hi(p1), h2 = bf_hi(p2), h3 = bf_hi(p3);
                const float h4 = bf_hi(p4), h5 = bf_hi(p5), h6 = bf_hi(p6), h7 = bf_hi(p7);
                aH[mt][0] = pack_bf2(h0, h1); aH[mt][1] = pack_bf2(h2, h3);
                aH[mt][2] = pack_bf2(h4, h5); aH[mt][3] = pack_bf2(h6, h7);
                aL[mt][0] = pack_bf2(p0 - h0, p1 - h1);
                aL[mt][1] = pack_bf2(p2 - h2, p3 - h3);
                aL[mt][2] = pack_bf2(p4 - h4, p5 - h5);
                aL[mt][3] = pack_bf2(p6 - h6, p7 - h7);
            }
#pragma unroll
            for (int np = 0; np < 2; ++np) {
                const int n = wn * 32 + np * 16 + b_n_off;
                uint32_t r[4];
                ldm_x4(sbB + n * 80 + (kk + b_k_off) * 2, r);
                bb[2 * np][0]     = r[0]; bb[2 * np][1]     = r[1];
                bb[2 * np + 1][0] = r[2]; bb[2 * np + 1][1] = r[3];
            }
#pragma unroll
            for (int mt = 0; mt < 2; ++mt)
#pragma unroll
                for (int nt = 0; nt < 4; ++nt)
                    mma_bf16(acc[mt][nt], aH[mt], bb[nt]);
#pragma unroll
            for (int mt = 0; mt < 2; ++mt)
#pragma unroll
                for (int nt = 0; nt < 4; ++nt)
                    mma_bf16(acc[mt][nt], aL[mt], bb[nt]);
#pragma unroll
            for (int np = 0; np < 2; ++np) {
                const int n = wn * 32 + np * 16 + b_n_off;
                uint32_t r[4];
                ldm_x4(sbB + AV_BBY + n * 80 + (kk + b_k_off) * 2, r);
                bb[2 * np][0]     = r[0]; bb[2 * np][1]     = r[1];
                bb[2 * np + 1][0] = r[2]; bb[2 * np + 1][1] = r[3];
            }
#pragma unroll
            for (int mt = 0; mt < 2; ++mt)
#pragma unroll
                for (int nt = 0; nt < 4; ++nt)
                    mma_bf16(acc[mt][nt], aH[mt], bb[nt]);
        }
        __syncthreads();
    }

    __nv_bfloat16* Oh = oh + ((size_t)b * SS) * DD + h * HD;
    __nv_bfloat16* Ol = ol + ((size_t)b * SS) * DD + h * HD;
    const int cb = wn * 32 + 2 * (lane & 3);
#pragma unroll
    for (int mt = 0; mt < 2; ++mt) {
        const int i0r = rr0 + mt * 16;
        const int i1r = i0r + 8;
#pragma unroll
        for (int nt = 0; nt < 4; ++nt) {
            const int col = cb + nt * 8;
            const float v0 = acc[mt][nt][0], v1 = acc[mt][nt][1];
            const float v2 = acc[mt][nt][2], v3 = acc[mt][nt][3];
            const float h0 = bf_hi(v0), h1 = bf_hi(v1);
            const float h2 = bf_hi(v2), h3 = bf_hi(v3);
            *(uint32_t*)&Oh[(size_t)i0r * DD + col] = pack_bf2(h0, h1);
            *(uint32_t*)&Oh[(size_t)i1r * DD + col] = pack_bf2(h2, h3);
            *(uint32_t*)&Ol[(size_t)i0r * DD + col] = pack_bf2(v0 - h0, v1 - h1);
            *(uint32_t*)&Ol[(size_t)i1r * DD + col] = pack_bf2(v2 - h2, v3 - h3);
        }
    }
}

// ---------------------------------------------------------------------------
// Weight transpose + bf16 hi/lo split (64x64 tiles, packed stores)
// ---------------------------------------------------------------------------
__global__ __launch_bounds__(256)
void conv_w(const float* __restrict__ W, __nv_bfloat16* __restrict__ hi,
            __nv_bfloat16* __restrict__ lo, int K, int N, long long lstride)
{
    __shared__ float t[64][65];   // [n][k]
    const int l = blockIdx.z;
    W  += (size_t)l * K * N;
    hi += (size_t)l * lstride;
    lo += (size_t)l * lstride;
    const int k0 = blockIdx.y * 64, n0 = blockIdx.x * 64;
    const int tid = threadIdx.x;
    const int tc = tid & 31;
    const int tr = tid >> 5;
#pragma unroll
    for (int i = 0; i < 8; ++i) {
        const int kk = tr + i * 8;
        const float2 v = *(const float2*)&W[(size_t)(k0 + kk) * N + n0 + tc * 2];
        t[tc * 2][kk]     = v.x;
        t[tc * 2 + 1][kk] = v.y;
    }
    __syncthreads();
    const int kp = (tid & 31) * 2;
    const int nb = tid >> 5;
#pragma unroll
    for (int i = 0; i < 8; ++i) {
        const int n = nb + i * 8;
        const float a = t[n][kp], b = t[n][kp + 1];
        const float ha = bf_hi(a), hb = bf_hi(b);
        *(uint32_t*)&hi[(size_t)(n0 + n) * K + k0 + kp] = pack_bf2(ha, hb);
        *(uint32_t*)&lo[(size_t)(n0 + n) * K + k0 + kp] = pack_bf2(a - ha, b - hb);
    }
}

// elementwise hi/lo split (for E)
__global__ void split_act(const float* __restrict__ x, __nv_bfloat16* __restrict__ hi,
                          __nv_bfloat16* __restrict__ lo, int n4)
{
    const int i = blockIdx.x * 256 + threadIdx.x;
    if (i >= n4) return;
    const float4 v = ((const float4*)x)[i];
    const float f[4] = {v.x, v.y, v.z, v.w};
    unsigned short hh[4], ll[4];
#pragma unroll
    for (int j = 0; j < 4; j++) {
        const __nv_bfloat16 hb = __float2bfloat16(f[j]);
        const __nv_bfloat16 lb = __float2bfloat16(f[j] - __bfloat162float(hb));
        hh[j] = __bfloat16_as_ushort(hb);
        ll[j] = __bfloat16_as_ushort(lb);
    }
    ((uint2*)hi)[i] = *(const uint2*)hh;
    ((uint2*)lo)[i] = *(const uint2*)ll;
}

// ---------------------------------------------------------------------------
// Sinusoid rate + embedding (writes split bf16 directly)
// ---------------------------------------------------------------------------
__global__ void rate_kernel(float* __restrict__ rate)
{
    const int d = blockIdx.x * 256 + threadIdx.x;
    if (d >= DD) return;
    const double LN1E4 = 9.210340371976184;
    const int par = d & 1;
    const float r1 = (float)exp(-LN1E4 * (double)d   / 1024.0);
    const float r2 = (float)exp( LN1E4 * (double)par / 1024.0);
    rate[d] = r1 * r2;
}

__global__ void embed_split(const int* __restrict__ x,
                            const float* __restrict__ emb,
                            const float* __restrict__ rate,
                            __nv_bfloat16* __restrict__ oh,
                            __nv_bfloat16* __restrict__ ol)
{
    const int bs = blockIdx.x;
    const int s  = bs & (SS - 1);
    const int tok = x[bs];
    const float* e = emb + (size_t)tok * DD;
    for (int d = threadIdx.x; d < DD; d += blockDim.x) {
        const int par = d & 1;
        const float ph = (float)s * rate[d] + 1.5707964f * (float)par;
        const float v = e[d] * 32.0f + sinf(ph);
        const __nv_bfloat16 hb = __float2bfloat16(v);
        oh[(size_t)bs * DD + d] = hb;
        ol[(size_t)bs * DD + d] = __float2bfloat16(v - __bfloat162float(hb));
    }
}

// ---------------------------------------------------------------------------
// LayerNorm over last dim (1024); reads fp32, writes SPLIT bf16.
// ---------------------------------------------------------------------------
__global__ __launch_bounds__(256)
void ln_split(const float* __restrict__ xin, const float* __restrict__ g,
              const float* __restrict__ be,
              __nv_bfloat16* __restrict__ oh, __nv_bfloat16* __restrict__ ol)
{
    const int row = blockIdx.x;
    const float* p = xin + (size_t)row * DD;
    const int t = threadIdx.x;
    float v[4];
    float s = 0.f, s2 = 0.f;
#pragma unroll
    for (int c = 0; c < 4; c++) {
        v[c] = p[t + c * 256];
        s += v[c];
        s2 += v[c] * v[c];
    }
    __shared__ float sh1[8], sh2[8];
#pragma unroll
    for (int o = 16; o > 0; o >>= 1) {
        s  += __shfl_xor_sync(0xffffffffu, s,  o);
        s2 += __shfl_xor_sync(0xffffffffu, s2, o);
    }
    if ((t & 31) == 0) { sh1[t >> 5] = s; sh2[t >> 5] = s2; }
    __syncthreads();
    s = 0.f; s2 = 0.f;
#pragma unroll
    for (int w = 0; w < 8; w++) { s += sh1[w]; s2 += sh2[w]; }
    const float mu  = s  * (1.f / DD);
    const float var = s2 * (1.f / DD) - mu * mu;
    const float inv = rsqrtf(var + 1e-6f);
#pragma unroll
    for (int c = 0; c < 4; c++) {
        const int d = t + c * 256;
        const float o = (v[c] - mu) * inv * g[d] + be[d];
        const __nv_bfloat16 hb = __float2bfloat16(o);
        oh[(size_t)row * DD + d] = hb;
        ol[(size_t)row * DD + d] = __float2bfloat16(o - __bfloat162float(hb));
    }
}

// ---------------------------------------------------------------------------
// Host side
// ---------------------------------------------------------------------------
using bf16 = __nv_bfloat16;

template<int BN, int SKIP, bool KCAP, int OUT, bool RELU>
static void run_mma_s(cudaStream_t st,
                      const bf16* ah, const bf16* al, const bf16* bh, const bf16* bl,
                      const float* bias, float* C, bf16* Ch, bf16* Cl,
                      int M, int N, int K, int lda, int ldb, int ldc,
                      int batch, int zdiv,
                      long long sA1, long long sA2,
                      long long sB1, long long sB2,
                      long long sC1, long long sC2)
{
    constexpr int STG = 2 * 10240 + 2 * BN * 80;
    static bool init = false;
    if (!init) {
        cudaFuncSetAttribute(gemm_mma<BN, SKIP, KCAP, OUT, RELU>,
                             cudaFuncAttributeMaxDynamicSharedMemorySize, 2 * STG);
        init = true;
    }
    dim3 grid(N / BN, M / 128, batch);
    gemm_mma<BN, SKIP, KCAP, OUT, RELU><<<grid, 256, 2 * STG, st>>>(
        ah, al, bh, bl, bias, C, Ch, Cl, K, lda, ldb, ldc,
        zdiv, sA1, sA2, sB1, sB2, sC1, sC2);
}

extern "C" void kernel_launch(void* const* d_in, const int* in_sizes, int n_in,
                              void* d_out, int out_size)
{
    const int*   x   = (const int*)  d_in[0];
    const float* emb = (const float*)d_in[1];
    const float* Wq  = (const float*)d_in[2];
    const float* bq  = (const float*)d_in[3];
    const float* Wk  = (const float*)d_in[4];
    const float* bk  = (const float*)d_in[5];
    const float* Wv  = (const float*)d_in[6];
    const float* bv  = (const float*)d_in[7];
    const float* Wo  = (const float*)d_in[8];
    const float* bo  = (const float*)d_in[9];
    const float* W1  = (const float*)d_in[10];
    const float* b1  = (const float*)d_in[11];
    const float* W2  = (const float*)d_in[12];
    const float* b2  = (const float*)d_in[13];
    const float* g1  = (const float*)d_in[14];
    const float* be1 = (const float*)d_in[15];
    const float* g2  = (const float*)d_in[16];
    const float* be2 = (const float*)d_in[17];
    const float* E   = (const float*)d_in[18];
    const float* Wf  = (const float*)d_in[19];
    const float* bf  = (const float*)d_in[20];
    float* out = (float*)d_out;

    static cudaStream_t s1 = nullptr;
    static cudaEvent_t evFork = nullptr, evJoin = nullptr, evK = nullptr, evV = nullptr;
    if (!s1) {
        cudaStreamCreateWithFlags(&s1, cudaStreamNonBlocking);
        cudaEventCreateWithFlags(&evFork, cudaEventDisableTiming);
        cudaEventCreateWithFlags(&evJoin, cudaEventDisableTiming);
        cudaEventCreateWithFlags(&evK,    cudaEventDisableTiming);
        cudaEventCreateWithFlags(&evV,    cudaEventDisableTiming);
    }
    cudaStream_t s0 = 0;

    cudaFuncSetAttribute(av_gemm, cudaFuncAttributeMaxDynamicSharedMemorySize,
                         AV_SMEM);

    float *t1, *h2, *qe, *lg, *rate, *ps;
    cudaGetSymbolAddress((void**)&t1, g_t1);
    cudaGetSymbolAddress((void**)&h2, g_h2);
    cudaGetSymbolAddress((void**)&qe, g_qe);
    cudaGetSymbolAddress((void**)&lg, g_lg);
    cudaGetSymbolAddress((void**)&rate, g_rate);
    cudaGetSymbolAddress((void**)&ps, g_ps);

    bf16 *xh, *xl, *qkh, *qkl, *vth, *vtl, *ath, *atl, *ffh, *ffl, *eh, *el;
    cudaGetSymbolAddress((void**)&xh,  g_xh);  cudaGetSymbolAddress((void**)&xl,  g_xl);
    cudaGetSymbolAddress((void**)&qkh, g_qkh); cudaGetSymbolAddress((void**)&qkl, g_qkl);
    cudaGetSymbolAddress((void**)&vth, g_vth); cudaGetSymbolAddress((void**)&vtl, g_vtl);
    cudaGetSymbolAddress((void**)&ath, g_ath); cudaGetSymbolAddress((void**)&atl, g_atl);
    cudaGetSymbolAddress((void**)&ffh, g_ffh); cudaGetSymbolAddress((void**)&ffl, g_ffl);
    cudaGetSymbolAddress((void**)&eh,  g_eh);  cudaGetSymbolAddress((void**)&el,  g_el);

    bf16 *wqkh, *wqkl, *wvh, *wvl, *woh, *wol;
    bf16 *w1h, *w1l, *w2h, *w2l, *wfh, *wfl;
    cudaGetSymbolAddress((void**)&wqkh, g_wqk_h); cudaGetSymbolAddress((void**)&wqkl, g_wqk_l);
    cudaGetSymbolAddress((void**)&wvh, g_wv_h); cudaGetSymbolAddress((void**)&wvl, g_wv_l);
    cudaGetSymbolAddress((void**)&woh, g_wo_h); cudaGetSymbolAddress((void**)&wol, g_wo_l);
    cudaGetSymbolAddress((void**)&w1h, g_w1_h); cudaGetSymbolAddress((void**)&w1l, g_w1_l);
    cudaGetSymbolAddress((void**)&w2h, g_w2_h); cudaGetSymbolAddress((void**)&w2l, g_w2_l);
    cudaGetSymbolAddress((void**)&wfh, g_wf_h); cudaGetSymbolAddress((void**)&wfl, g_wf_l);

    const int M = BB * SS;  // 2048
    const long long sSD  = (long long)SS * DD;
    const long long sSQK = (long long)SS * QKW;
    const long long sHSS = (long long)HH * SS * SS;
    const long long sSSq = (long long)SS * SS;
    const long long sDS  = (long long)DD * SS;
    const long long wQKL = (long long)QKW * DD;

    // ---- setup: conversions on s0 || {rest, rate, embed} on s1
    cudaEventRecord(evFork, s0);
    cudaStreamWaitEvent(s1, evFork, 0);

    conv_w<<<dim3(DD / 64, DD / 64, LL), 256, 0, s0>>>(Wq, wqkh, wqkl, DD, DD, wQKL);
    conv_w<<<dim3(DD / 64, DD / 64, LL), 256, 0, s0>>>(Wk, wqkh + (size_t)DD * DD,
                                                       wqkl + (size_t)DD * DD, DD, DD, wQKL);
    conv_w<<<dim3(DD / 64, DD / 64, LL), 256, 0, s0>>>(Wv, wvh, wvl, DD, DD, (long long)DD * DD);

    conv_w<<<dim3(DD / 64, DD / 64, LL), 256, 0, s1>>>(Wo, woh, wol, DD, DD, (long long)DD * DD);
    conv_w<<<dim3(DF / 64, DD / 64, LL), 256, 0, s1>>>(W1, w1h, w1l, DD, DF, (long long)DF * DD);
    conv_w<<<dim3(DD / 64, DF / 64, LL), 256, 0, s1>>>(W2, w2h, w2l, DF, DD, (long long)DD * DF);
    conv_w<<<dim3(VV / 64, DD / 64, 1),  256, 0, s1>>>(Wf, wfh, wfl, DD, VV, (long long)VV * DD);
    split_act<<<(LL * SS * HD / 4 + 255) / 256, 256, 0, s1>>>(E, eh, el, LL * SS * HD / 4);
    rate_kernel<<<4, 256, 0, s1>>>(rate);
    embed_split<<<BB * SS, 256, 0, s1>>>(x, emb, rate, xh, xl);

    cudaEventRecord(evJoin, s1);
    cudaStreamWaitEvent(s0, evJoin, 0);

    for (int l = 0; l < LL; l++) {
        const size_t wdd = (size_t)l * DD * DD;
        const size_t wdf = (size_t)l * DF * DD;
        const bf16* ehl = eh + (size_t)l * SS * HD;
        const bf16* ell = el + (size_t)l * SS * HD;

        // fork: K-proj + V-proj on s1, Q-proj -> QE -> QK on s0
        cudaEventRecord(evFork, s0);
        cudaStreamWaitEvent(s1, evFork, 0);

        // Q projection (columns 0..1023 of qk buffer)
        run_mma_s<128, 0, false, 1, false>(s0, xh, xl, wqkh + (size_t)l * wQKL,
                                           wqkl + (size_t)l * wQKL, bq + l * DD,
                                           nullptr, qkh, qkl, M, DD, DD, DD, DD, QKW,
                                           1, 1, 0, 0, 0, 0, 0, 0);

        // K projection (columns 1024..2047) on s1
        run_mma_s<128, 0, false, 1, false>(s1, xh, xl,
                                           wqkh + (size_t)l * wQKL + (size_t)DD * DD,
                                           wqkl + (size_t)l * wQKL + (size_t)DD * DD,
                                           bk + l * DD,
                                           nullptr, qkh + DD, qkl + DD,
                                           M, DD, DD, DD, DD, QKW,
                                           1, 1, 0, 0, 0, 0, 0, 0);
        cudaEventRecord(evK, s1);
        // V projection (split-transposed per batch) on s1
        run_mma_s<128, 0, false, 2, false>(s1, xh, xl, wvh + wdd, wvl + wdd, bv + l * DD,
                                           nullptr, vth, vtl, SS, DD, DD, DD, DD, SS,
                                           BB, 1, sSD, 0, 0, 0, sDS, 0);
        cudaEventRecord(evV, s1);

        // QE (anti-diagonal tiles only) on s0 -- needs q only
        run_mma_s<128, 1, false, 0, false>(s0, qkh, qkl, ehl, ell, nullptr, qe,
                                           nullptr, nullptr,
                                           SS, SS, HD, QKW, HD, SS, BB * HH, HH,
                                           sSQK, HD, 0, 0, sHSS, sSSq);

        // QK^T with fused Srel + masks + exp + sumexp partials (OUT=3)
        cudaStreamWaitEvent(s0, evK, 0);
        run_mma_s<128, 2, false, 3, false>(s0, qkh, qkl, qkh + DD, qkl + DD,
                                           (const float*)x, lg, (bf16*)qe, (bf16*)ps,
                                           SS, SS, HD, QKW, QKW, SS, BB * HH, HH,
                                           sSQK, HD, sSQK, HD, sHSS, sSSq);

        // attn = P @ v, inline invS (heavy tiles first)
        cudaStreamWaitEvent(s0, evV, 0);
        av_gemm<<<dim3(1, SS / 128, BB * HH), 256, AV_SMEM, s0>>>(
            lg, ps, vth, vtl, ath, atl);

        // Wo + LN1
        run_mma_s<128, 0, false, 0, false>(s0, ath, atl, woh + wdd, wol + wdd, bo + l * DD,
                                           t1, nullptr, nullptr, M, DD, DD, DD, DD, DD,
                                           1, 1, 0, 0, 0, 0, 0, 0);
        ln_split<<<BB * SS, 256, 0, s0>>>(t1, g1 + l * DD, be1 + l * DD, xh, xl);

        // FFN
        run_mma_s<64, 0, false, 1, true>(s0, xh, xl, w1h + wdf, w1l + wdf, b1 + l * DF,
                                         nullptr, ffh, ffl, M, DF, DD, DD, DD, DF,
                                         1, 1, 0, 0, 0, 0, 0, 0);
        run_mma_s<128, 0, false, 0, false>(s0, ffh, ffl, w2h + wdf, w2l + wdf, b2 + l * DD,
                                           h2, nullptr, nullptr, M, DD, DF, DF, DF, DD,
                                           1, 1, 0, 0, 0, 0, 0, 0);
        ln_split<<<BB * SS, 256, 0, s0>>>(h2, g2 + l * DD, be2 + l * DD, xh, xl);
    }

    // final projection to vocab
    run_mma_s<64, 0, false, 0, false>(s0, xh, xl, wfh, wfl, bf, out, nullptr, nullptr,
                                      M, VV, DD, DD, DD, VV, 1, 1, 0, 0, 0, 0, 0, 0);
}